// round 1
// baseline (speedup 1.0000x reference)
#include <cuda_runtime.h>
#include <math.h>

// Problem constants
constexpr int BB = 2;
constexpr int TT = 2048;
constexpr int DD = 1024;
constexpr int HH = 16;
constexpr int DH = 64;
constexpr int MROWS = BB * TT;          // 4096
constexpr int QKV_N = 3 * DD;           // 3072

// Scratch (static device allocations — sanctioned workaround, no cudaMalloc)
__device__ float g_qkv[MROWS * QKV_N];   // [4096][3072], q|k|v interleaved per row
__device__ float g_attn[MROWS * DD];     // [B,T, H*DH] attention output

// ---------------------------------------------------------------------------
// SGEMM: C[M,N] = A[M,K] @ B[K,N] + bias[N]
// 128x128 tile, BK=8, 256 threads, 8x8 microtile (4+4 split rows/cols)
// ---------------------------------------------------------------------------
__device__ __forceinline__ void sgemm_bias_body(
    const float* __restrict__ A, const float* __restrict__ Bm,
    const float* __restrict__ bias, float* __restrict__ C,
    int M, int N, int K)
{
    constexpr int BM = 128, BN = 128, BK = 8;
    __shared__ float sA[BK][BM];
    __shared__ float sB[BK][BN];

    const int tid = threadIdx.x;
    const int tx = tid & 15;
    const int ty = tid >> 4;
    const int r0 = ty * 4, r1 = 64 + ty * 4;
    const int c0 = tx * 4, c1 = 64 + tx * 4;

    const float* Ab = A + (size_t)blockIdx.y * BM * K;
    const float* Bb = Bm + (size_t)blockIdx.x * BN;

    const int a_r = tid >> 1, a_c = (tid & 1) * 4;   // A tile 128x8
    const int b_r = tid >> 5, b_c = (tid & 31) * 4;  // B tile 8x128

    float acc[8][8];
#pragma unroll
    for (int i = 0; i < 8; i++)
#pragma unroll
        for (int j = 0; j < 8; j++) acc[i][j] = 0.f;

    for (int k0 = 0; k0 < K; k0 += BK) {
        float4 av = *(const float4*)(Ab + (size_t)a_r * K + k0 + a_c);
        float4 bv = *(const float4*)(Bb + (size_t)(k0 + b_r) * N + b_c);
        __syncthreads();
        sA[a_c + 0][a_r] = av.x;
        sA[a_c + 1][a_r] = av.y;
        sA[a_c + 2][a_r] = av.z;
        sA[a_c + 3][a_r] = av.w;
        *(float4*)&sB[b_r][b_c] = bv;
        __syncthreads();
#pragma unroll
        for (int kk = 0; kk < BK; kk++) {
            float a[8], bb[8];
            *(float4*)(a)      = *(const float4*)&sA[kk][r0];
            *(float4*)(a + 4)  = *(const float4*)&sA[kk][r1];
            *(float4*)(bb)     = *(const float4*)&sB[kk][c0];
            *(float4*)(bb + 4) = *(const float4*)&sB[kk][c1];
#pragma unroll
            for (int i = 0; i < 8; i++)
#pragma unroll
                for (int j = 0; j < 8; j++)
                    acc[i][j] += a[i] * bb[j];
        }
    }

    float bset[8];
#pragma unroll
    for (int j = 0; j < 4; j++) {
        bset[j]     = bias[blockIdx.x * BN + c0 + j];
        bset[4 + j] = bias[blockIdx.x * BN + c1 + j];
    }
#pragma unroll
    for (int i = 0; i < 8; i++) {
        int row = (i < 4) ? (r0 + i) : (r1 + i - 4);
        float* Crow = C + (size_t)(blockIdx.y * BM + row) * N + blockIdx.x * BN;
        float4 v0 = make_float4(acc[i][0] + bset[0], acc[i][1] + bset[1],
                                acc[i][2] + bset[2], acc[i][3] + bset[3]);
        float4 v1 = make_float4(acc[i][4] + bset[4], acc[i][5] + bset[5],
                                acc[i][6] + bset[6], acc[i][7] + bset[7]);
        *(float4*)(Crow + c0) = v0;
        *(float4*)(Crow + c1) = v1;
    }
}

__global__ __launch_bounds__(256) void gemm_qkv_kernel(
    const float* __restrict__ x, const float* __restrict__ w,
    const float* __restrict__ bias)
{
    sgemm_bias_body(x, w, bias, g_qkv, MROWS, QKV_N, DD);
}

__global__ __launch_bounds__(256) void gemm_out_kernel(
    const float* __restrict__ w, const float* __restrict__ bias,
    float* __restrict__ out)
{
    sgemm_bias_body(g_attn, w, bias, out, MROWS, DD, DD);
}

// ---------------------------------------------------------------------------
// Flash attention, fp32, causal. Block: 128 Q rows of one (b,h); 256 threads.
// KV tiles of 64. Thread (tr,tc): rows {4tr..4tr+3, 64+4tr..+3}, cols 4tc..+3.
// smem layouts (k/c-major where the hot b-side load must be contiguous):
//   sQ[d][r]  stride 132,  sK[d][c] stride 68,  sV[c][d] stride 68, sP[c][r] 132
// ---------------------------------------------------------------------------
constexpr int FA_BM = 128;
constexpr int FA_BN = 64;
constexpr int SQ_S = 132, SK_S = 68, SV_S = 68, SP_S = 132;
constexpr int FA_SMEM_FLOATS = 64 * SQ_S + 64 * SK_S + 64 * SV_S + 64 * SP_S; // 25600
constexpr int FA_SMEM_BYTES = FA_SMEM_FLOATS * 4; // 102400

__global__ __launch_bounds__(256) void flash_attn_kernel()
{
    extern __shared__ float smem[];
    float* sQ = smem;
    float* sK = sQ + 64 * SQ_S;
    float* sV = sK + 64 * SK_S;
    float* sP = sV + 64 * SV_S;

    const int tid = threadIdx.x;
    const int tc = tid & 15;
    const int tr = tid >> 4;
    const int bh = blockIdx.y;
    const int b = bh >> 4;        // H = 16
    const int h = bh & 15;
    const int i0 = blockIdx.x * FA_BM;

    const float* qb = g_qkv + (size_t)b * TT * QKV_N + h * DH;
    const float* kb = qb + DD;
    const float* vb = qb + 2 * DD;

    // Load Q tile (pre-scaled by 1/sqrt(DH) = 0.125)
#pragma unroll
    for (int it = 0; it < 8; ++it) {
        int idx = it * 256 + tid;
        int d4 = (idx & 15) << 2;
        int r = idx >> 4;
        float4 v = *(const float4*)(qb + (size_t)(i0 + r) * QKV_N + d4);
        sQ[(d4 + 0) * SQ_S + r] = v.x * 0.125f;
        sQ[(d4 + 1) * SQ_S + r] = v.y * 0.125f;
        sQ[(d4 + 2) * SQ_S + r] = v.z * 0.125f;
        sQ[(d4 + 3) * SQ_S + r] = v.w * 0.125f;
    }

    float o[8][4];
    float m[8], l[8];
#pragma unroll
    for (int i = 0; i < 8; i++) {
        m[i] = -1e30f;
        l[i] = 0.f;
#pragma unroll
        for (int j = 0; j < 4; j++) o[i][j] = 0.f;
    }
    int rows[8];
#pragma unroll
    for (int i = 0; i < 4; i++) {
        rows[i] = 4 * tr + i;
        rows[i + 4] = 64 + 4 * tr + i;
    }

    for (int j0 = 0; j0 < i0 + FA_BM; j0 += FA_BN) {
        __syncthreads();  // prev PV done reading sP/sV
        // Load K (transposed, d-major) and V (c-major)
#pragma unroll
        for (int it = 0; it < 4; ++it) {
            int idx = it * 256 + tid;
            int d4 = (idx & 15) << 2;
            int c = idx >> 4;
            float4 kv = *(const float4*)(kb + (size_t)(j0 + c) * QKV_N + d4);
            sK[(d4 + 0) * SK_S + c] = kv.x;
            sK[(d4 + 1) * SK_S + c] = kv.y;
            sK[(d4 + 2) * SK_S + c] = kv.z;
            sK[(d4 + 3) * SK_S + c] = kv.w;
            float4 vv = *(const float4*)(vb + (size_t)(j0 + c) * QKV_N + d4);
            *(float4*)&sV[c * SV_S + d4] = vv;
        }
        __syncthreads();

        // S = Q @ K^T  (scale already folded into Q)
        float s[8][4];
#pragma unroll
        for (int i = 0; i < 8; i++)
#pragma unroll
            for (int j = 0; j < 4; j++) s[i][j] = 0.f;

#pragma unroll 4
        for (int k = 0; k < DH; k++) {
            float a[8], bv[4];
            *(float4*)(a)     = *(const float4*)&sQ[k * SQ_S + 4 * tr];
            *(float4*)(a + 4) = *(const float4*)&sQ[k * SQ_S + 64 + 4 * tr];
            *(float4*)(bv)    = *(const float4*)&sK[k * SK_S + 4 * tc];
#pragma unroll
            for (int i = 0; i < 8; i++)
#pragma unroll
                for (int j = 0; j < 4; j++)
                    s[i][j] += a[i] * bv[j];
        }

        // Causal mask (only diagonal-overlapping tiles)
        if (j0 + FA_BN > i0) {
#pragma unroll
            for (int i = 0; i < 8; i++) {
                int qi = i0 + rows[i];
#pragma unroll
                for (int j = 0; j < 4; j++) {
                    int ki = j0 + 4 * tc + j;
                    if (ki > qi) s[i][j] = -1e30f;
                }
            }
        }

        // Online softmax update + write P (in s regs) to smem
#pragma unroll
        for (int i = 0; i < 8; i++) {
            float tmax = fmaxf(fmaxf(s[i][0], s[i][1]), fmaxf(s[i][2], s[i][3]));
            tmax = fmaxf(tmax, __shfl_xor_sync(0xffffffffu, tmax, 1));
            tmax = fmaxf(tmax, __shfl_xor_sync(0xffffffffu, tmax, 2));
            tmax = fmaxf(tmax, __shfl_xor_sync(0xffffffffu, tmax, 4));
            tmax = fmaxf(tmax, __shfl_xor_sync(0xffffffffu, tmax, 8));
            float mnew = fmaxf(m[i], tmax);
            float alpha = __expf(m[i] - mnew);
            float psum = 0.f;
#pragma unroll
            for (int j = 0; j < 4; j++) {
                float p = __expf(s[i][j] - mnew);
                s[i][j] = p;
                psum += p;
            }
            psum += __shfl_xor_sync(0xffffffffu, psum, 1);
            psum += __shfl_xor_sync(0xffffffffu, psum, 2);
            psum += __shfl_xor_sync(0xffffffffu, psum, 4);
            psum += __shfl_xor_sync(0xffffffffu, psum, 8);
            l[i] = l[i] * alpha + psum;
            m[i] = mnew;
#pragma unroll
            for (int j = 0; j < 4; j++) o[i][j] *= alpha;
#pragma unroll
            for (int j = 0; j < 4; j++)
                sP[(4 * tc + j) * SP_S + rows[i]] = s[i][j];
        }
        __syncthreads();

        // O += P @ V
#pragma unroll 4
        for (int c = 0; c < FA_BN; c++) {
            float a[8], bv[4];
            *(float4*)(a)     = *(const float4*)&sP[c * SP_S + 4 * tr];
            *(float4*)(a + 4) = *(const float4*)&sP[c * SP_S + 64 + 4 * tr];
            *(float4*)(bv)    = *(const float4*)&sV[c * SV_S + 4 * tc];
#pragma unroll
            for (int i = 0; i < 8; i++)
#pragma unroll
                for (int j = 0; j < 4; j++)
                    o[i][j] += a[i] * bv[j];
        }
    }

    // Normalize and write out in [B,T,H*DH] layout
#pragma unroll
    for (int i = 0; i < 8; i++) {
        float inv = 1.0f / l[i];
        int t = i0 + rows[i];
        float4 v = make_float4(o[i][0] * inv, o[i][1] * inv,
                               o[i][2] * inv, o[i][3] * inv);
        *(float4*)(g_attn + (size_t)(b * TT + t) * DD + h * DH + 4 * tc) = v;
    }
}

// ---------------------------------------------------------------------------
extern "C" void kernel_launch(void* const* d_in, const int* in_sizes, int n_in,
                              void* d_out, int out_size)
{
    const float* x     = (const float*)d_in[0];
    const float* w_qkv = (const float*)d_in[1];
    const float* b_qkv = (const float*)d_in[2];
    const float* w_out = (const float*)d_in[3];
    const float* b_out = (const float*)d_in[4];
    float* out = (float*)d_out;

    cudaFuncSetAttribute(flash_attn_kernel,
                         cudaFuncAttributeMaxDynamicSharedMemorySize,
                         FA_SMEM_BYTES);

    dim3 g1(QKV_N / 128, MROWS / 128);   // 24 x 32
    gemm_qkv_kernel<<<g1, 256>>>(x, w_qkv, b_qkv);

    dim3 g2(TT / FA_BM, BB * HH);        // 16 x 32
    flash_attn_kernel<<<g2, 256, FA_SMEM_BYTES>>>();

    dim3 g3(DD / 128, MROWS / 128);      // 8 x 32
    gemm_out_kernel<<<g3, 256>>>(w_out, b_out, out);
}

// round 3
// speedup vs baseline: 1.3490x; 1.3490x over previous
#include <cuda_runtime.h>
#include <cuda_bf16.h>
#include <math.h>
#include <stdint.h>

// Problem constants
constexpr int BB = 2;
constexpr int TT = 2048;
constexpr int DD = 1024;
constexpr int HH = 16;
constexpr int DH = 64;
constexpr int MROWS = BB * TT;          // 4096
constexpr int QKV_N = 3 * DD;           // 3072

// ---------------------------------------------------------------------------
// Scratch (static device allocations — no cudaMalloc allowed)
// ---------------------------------------------------------------------------
__device__ float g_qkv[MROWS * QKV_N];     // [4096][3072] q|k|v per row
__device__ float g_attn[MROWS * DD];       // [B,T,H*DH] attention output
__device__ __nv_bfloat16 g_x_hi[MROWS * DD],  g_x_lo[MROWS * DD];    // x split
__device__ __nv_bfloat16 g_wq_hi[QKV_N * DD], g_wq_lo[QKV_N * DD];   // w_qkv^T [N,K]
__device__ __nv_bfloat16 g_wo_hi[DD * DD],    g_wo_lo[DD * DD];      // w_out^T [N,K]
__device__ __nv_bfloat16 g_a_hi[MROWS * DD],  g_a_lo[MROWS * DD];    // attn split

// ---------------------------------------------------------------------------
// PTX helpers (sm_80-era: supported at target sm_103)
// ---------------------------------------------------------------------------
__device__ __forceinline__ uint32_t smem_u32(const void* p) {
    return (uint32_t)__cvta_generic_to_shared((void*)p);
}

__device__ __forceinline__ void cp16(uint32_t dst, const void* src) {
    asm volatile("cp.async.cg.shared.global [%0], [%1], 16;" :: "r"(dst), "l"(src));
}

__device__ __forceinline__ void ldsm4(uint32_t* r, uint32_t addr) {
    asm volatile("ldmatrix.sync.aligned.m8n8.x4.shared.b16 {%0,%1,%2,%3}, [%4];"
                 : "=r"(r[0]), "=r"(r[1]), "=r"(r[2]), "=r"(r[3]) : "r"(addr));
}

__device__ __forceinline__ void mma_bf16(float* d, const uint32_t* a,
                                         uint32_t b0, uint32_t b1) {
    asm volatile(
        "mma.sync.aligned.m16n8k16.row.col.f32.bf16.bf16.f32 "
        "{%0,%1,%2,%3}, {%4,%5,%6,%7}, {%8,%9}, {%0,%1,%2,%3};"
        : "+f"(d[0]), "+f"(d[1]), "+f"(d[2]), "+f"(d[3])
        : "r"(a[0]), "r"(a[1]), "r"(a[2]), "r"(a[3]), "r"(b0), "r"(b1));
}

// ---------------------------------------------------------------------------
// Split conversions (fp32 -> bf16 hi + bf16 lo)
// ---------------------------------------------------------------------------
__global__ __launch_bounds__(256) void split_kernel(
    const float* __restrict__ in, __nv_bfloat16* __restrict__ hi,
    __nv_bfloat16* __restrict__ lo, int n4)
{
    int i = blockIdx.x * blockDim.x + threadIdx.x;
    if (i >= n4) return;
    float4 v = ((const float4*)in)[i];
    __nv_bfloat16 h0 = __float2bfloat16(v.x);
    __nv_bfloat16 h1 = __float2bfloat16(v.y);
    __nv_bfloat16 h2 = __float2bfloat16(v.z);
    __nv_bfloat16 h3 = __float2bfloat16(v.w);
    __nv_bfloat16 l0 = __float2bfloat16(v.x - __bfloat162float(h0));
    __nv_bfloat16 l1 = __float2bfloat16(v.y - __bfloat162float(h1));
    __nv_bfloat16 l2 = __float2bfloat16(v.z - __bfloat162float(h2));
    __nv_bfloat16 l3 = __float2bfloat16(v.w - __bfloat162float(h3));
    ((__nv_bfloat162*)hi)[2 * i]     = __nv_bfloat162(h0, h1);
    ((__nv_bfloat162*)hi)[2 * i + 1] = __nv_bfloat162(h2, h3);
    ((__nv_bfloat162*)lo)[2 * i]     = __nv_bfloat162(l0, l1);
    ((__nv_bfloat162*)lo)[2 * i + 1] = __nv_bfloat162(l2, l3);
}

// in: [K, N] fp32 row-major -> out hi/lo: [N, K] bf16 row-major
__global__ __launch_bounds__(256) void transpose_split_kernel(
    const float* __restrict__ in, __nv_bfloat16* __restrict__ hi,
    __nv_bfloat16* __restrict__ lo, int K, int N)
{
    __shared__ float tile[32][33];
    int n0 = blockIdx.x * 32, k0 = blockIdx.y * 32;
    int tx = threadIdx.x & 31, ty = threadIdx.x >> 5;
#pragma unroll
    for (int j = 0; j < 32; j += 8)
        tile[ty + j][tx] = in[(size_t)(k0 + ty + j) * N + n0 + tx];
    __syncthreads();
#pragma unroll
    for (int j = 0; j < 32; j += 8) {
        float v = tile[tx][ty + j];
        __nv_bfloat16 h = __float2bfloat16(v);
        __nv_bfloat16 l = __float2bfloat16(v - __bfloat162float(h));
        size_t o = (size_t)(n0 + ty + j) * K + k0 + tx;
        hi[o] = h;
        lo[o] = l;
    }
}

// ---------------------------------------------------------------------------
// mma.sync bf16-split GEMM: C[M,N] = A[M,K] @ B[N,K]^T + bias
// 128x128 CTA tile, BK=32, 256 threads (8 warps, 4m x 2n), warp tile 32x64.
// smem: 2 stages x {Ahi, Alo, Bhi, Blo}, each 128 rows x 40 bf16 (80B stride).
// ---------------------------------------------------------------------------
constexpr int GK = 32;                 // K chunk (bf16)
constexpr int NCHUNK = DD / GK;        // 32
constexpr int ROW_B = 80;              // smem row stride bytes (40 bf16)
constexpr int TILE_SM = 128 * ROW_B;   // 10240 B
constexpr int STAGE_SM = 4 * TILE_SM;  // 40960 B
constexpr int GEMM_SMEM = 2 * STAGE_SM; // 81920 B

__global__ __launch_bounds__(256, 1) void gemm_mma_kernel(
    const __nv_bfloat16* __restrict__ Ahi, const __nv_bfloat16* __restrict__ Alo,
    const __nv_bfloat16* __restrict__ Bhi, const __nv_bfloat16* __restrict__ Blo,
    const float* __restrict__ bias, float* __restrict__ C, int N)
{
    extern __shared__ char sm[];
    const uint32_t smb = smem_u32(sm);
    const int tid = threadIdx.x;
    const int wid = tid >> 5, lane = tid & 31;
    const int wm = wid >> 1, wn = wid & 1;     // 4 x 2 warp grid
    const int m0 = blockIdx.y * 128;
    const int n0 = blockIdx.x * 128;

    const char* Ahp = (const char*)Ahi + (size_t)m0 * DD * 2;
    const char* Alp = (const char*)Alo + (size_t)m0 * DD * 2;
    const char* Bhp = (const char*)Bhi + (size_t)n0 * DD * 2;
    const char* Blp = (const char*)Blo + (size_t)n0 * DD * 2;

    // per-thread load slots: 2 chunks of 16B per tile per stage
    const int r_ld[2]  = { (0 * 256 + tid) >> 2, (1 * 256 + tid) >> 2 };
    const int c4_ld[2] = { (0 * 256 + tid) & 3,  (1 * 256 + tid) & 3 };

    auto load_stage = [&](int c, int s) {
        const int k0b = c * GK * 2;            // byte offset along K
        const uint32_t sb = smb + s * STAGE_SM;
#pragma unroll
        for (int i = 0; i < 2; ++i) {
            const int r = r_ld[i], c4 = c4_ld[i];
            const size_t g = (size_t)r * (DD * 2) + k0b + c4 * 16;
            const uint32_t so = r * ROW_B + c4 * 16;
            cp16(sb + so,               Ahp + g);
            cp16(sb + TILE_SM + so,     Alp + g);
            cp16(sb + 2 * TILE_SM + so, Bhp + g);
            cp16(sb + 3 * TILE_SM + so, Blp + g);
        }
        asm volatile("cp.async.commit_group;" ::: "memory");
    };

    float acc[2][8][4];
#pragma unroll
    for (int mt = 0; mt < 2; ++mt)
#pragma unroll
        for (int nt = 0; nt < 8; ++nt)
#pragma unroll
            for (int j = 0; j < 4; ++j) acc[mt][nt][j] = 0.f;

    // ldmatrix lane addressing (precomputed offsets within a stage)
    const int a_row = wm * 32 + (lane & 15);          // + mt*16
    const int a_kb  = (lane >> 4) * 16;               // +k16*32 bytes
    const int b_row = wn * 64 + (lane & 7) + ((lane >> 4) << 3);  // + p*16
    const int b_kb  = ((lane >> 3) & 1) * 16;         // +k16*32 bytes

    load_stage(0, 0);

    for (int c = 0; c < NCHUNK; ++c) {
        if (c + 1 < NCHUNK) {
            load_stage(c + 1, (c + 1) & 1);
            asm volatile("cp.async.wait_group 1;" ::: "memory");
        } else {
            asm volatile("cp.async.wait_group 0;" ::: "memory");
        }
        __syncthreads();

        const uint32_t sb = smb + (c & 1) * STAGE_SM;
#pragma unroll
        for (int k16 = 0; k16 < 2; ++k16) {
            const int kb = k16 * 32;  // 16 bf16 = 32 bytes
            uint32_t ah[2][4], al[2][4], bh[4][4], bl[4][4];
#pragma unroll
            for (int mt = 0; mt < 2; ++mt) {
                uint32_t addr = sb + (a_row + mt * 16) * ROW_B + kb + a_kb;
                ldsm4(ah[mt], addr);
                ldsm4(al[mt], addr + TILE_SM);
            }
#pragma unroll
            for (int p = 0; p < 4; ++p) {
                uint32_t addr = sb + 2 * TILE_SM +
                                (b_row + p * 16) * ROW_B + kb + b_kb;
                ldsm4(bh[p], addr);
                ldsm4(bl[p], addr + TILE_SM);
            }
#pragma unroll
            for (int mt = 0; mt < 2; ++mt)
#pragma unroll
                for (int nt = 0; nt < 8; ++nt) {
                    const int p = nt >> 1, h = (nt & 1) * 2;
                    mma_bf16(acc[mt][nt], ah[mt], bh[p][h], bh[p][h + 1]);
                    mma_bf16(acc[mt][nt], ah[mt], bl[p][h], bl[p][h + 1]);
                    mma_bf16(acc[mt][nt], al[mt], bh[p][h], bh[p][h + 1]);
                }
        }
        __syncthreads();
    }

    // Epilogue: add bias, store fp32
#pragma unroll
    for (int mt = 0; mt < 2; ++mt) {
        const int r0 = m0 + wm * 32 + mt * 16 + (lane >> 2);
#pragma unroll
        for (int nt = 0; nt < 8; ++nt) {
            const int cc = n0 + wn * 64 + nt * 8 + (lane & 3) * 2;
            const float2 b2 = *(const float2*)(bias + cc);
            float2 v0 = make_float2(acc[mt][nt][0] + b2.x, acc[mt][nt][1] + b2.y);
            float2 v1 = make_float2(acc[mt][nt][2] + b2.x, acc[mt][nt][3] + b2.y);
            *(float2*)(C + (size_t)r0 * N + cc) = v0;
            *(float2*)(C + (size_t)(r0 + 8) * N + cc) = v1;
        }
    }
}

// ---------------------------------------------------------------------------
// Flash attention, fp32, causal (unchanged — verified round 1)
// ---------------------------------------------------------------------------
constexpr int FA_BM = 128;
constexpr int FA_BN = 64;
constexpr int SQ_S = 132, SK_S = 68, SV_S = 68, SP_S = 132;
constexpr int FA_SMEM_FLOATS = 64 * SQ_S + 64 * SK_S + 64 * SV_S + 64 * SP_S;
constexpr int FA_SMEM_BYTES = FA_SMEM_FLOATS * 4;  // 102400

__global__ __launch_bounds__(256) void flash_attn_kernel()
{
    extern __shared__ float smem[];
    float* sQ = smem;
    float* sK = sQ + 64 * SQ_S;
    float* sV = sK + 64 * SK_S;
    float* sP = sV + 64 * SV_S;

    const int tid = threadIdx.x;
    const int tc = tid & 15;
    const int tr = tid >> 4;
    const int bh = blockIdx.y;
    const int b = bh >> 4;
    const int h = bh & 15;
    const int i0 = blockIdx.x * FA_BM;

    const float* qb = g_qkv + (size_t)b * TT * QKV_N + h * DH;
    const float* kb = qb + DD;
    const float* vb = qb + 2 * DD;

#pragma unroll
    for (int it = 0; it < 8; ++it) {
        int idx = it * 256 + tid;
        int d4 = (idx & 15) << 2;
        int r = idx >> 4;
        float4 v = *(const float4*)(qb + (size_t)(i0 + r) * QKV_N + d4);
        sQ[(d4 + 0) * SQ_S + r] = v.x * 0.125f;
        sQ[(d4 + 1) * SQ_S + r] = v.y * 0.125f;
        sQ[(d4 + 2) * SQ_S + r] = v.z * 0.125f;
        sQ[(d4 + 3) * SQ_S + r] = v.w * 0.125f;
    }

    float o[8][4];
    float m[8], l[8];
#pragma unroll
    for (int i = 0; i < 8; i++) {
        m[i] = -1e30f;
        l[i] = 0.f;
#pragma unroll
        for (int j = 0; j < 4; j++) o[i][j] = 0.f;
    }
    int rows[8];
#pragma unroll
    for (int i = 0; i < 4; i++) {
        rows[i] = 4 * tr + i;
        rows[i + 4] = 64 + 4 * tr + i;
    }

    for (int j0 = 0; j0 < i0 + FA_BM; j0 += FA_BN) {
        __syncthreads();
#pragma unroll
        for (int it = 0; it < 4; ++it) {
            int idx = it * 256 + tid;
            int d4 = (idx & 15) << 2;
            int c = idx >> 4;
            float4 kv = *(const float4*)(kb + (size_t)(j0 + c) * QKV_N + d4);
            sK[(d4 + 0) * SK_S + c] = kv.x;
            sK[(d4 + 1) * SK_S + c] = kv.y;
            sK[(d4 + 2) * SK_S + c] = kv.z;
            sK[(d4 + 3) * SK_S + c] = kv.w;
            float4 vv = *(const float4*)(vb + (size_t)(j0 + c) * QKV_N + d4);
            *(float4*)&sV[c * SV_S + d4] = vv;
        }
        __syncthreads();

        float s[8][4];
#pragma unroll
        for (int i = 0; i < 8; i++)
#pragma unroll
            for (int j = 0; j < 4; j++) s[i][j] = 0.f;

#pragma unroll 4
        for (int k = 0; k < DH; k++) {
            float a[8], bv[4];
            *(float4*)(a)     = *(const float4*)&sQ[k * SQ_S + 4 * tr];
            *(float4*)(a + 4) = *(const float4*)&sQ[k * SQ_S + 64 + 4 * tr];
            *(float4*)(bv)    = *(const float4*)&sK[k * SK_S + 4 * tc];
#pragma unroll
            for (int i = 0; i < 8; i++)
#pragma unroll
                for (int j = 0; j < 4; j++)
                    s[i][j] += a[i] * bv[j];
        }

        if (j0 + FA_BN > i0) {
#pragma unroll
            for (int i = 0; i < 8; i++) {
                int qi = i0 + rows[i];
#pragma unroll
                for (int j = 0; j < 4; j++) {
                    int ki = j0 + 4 * tc + j;
                    if (ki > qi) s[i][j] = -1e30f;
                }
            }
        }

#pragma unroll
        for (int i = 0; i < 8; i++) {
            float tmax = fmaxf(fmaxf(s[i][0], s[i][1]), fmaxf(s[i][2], s[i][3]));
            tmax = fmaxf(tmax, __shfl_xor_sync(0xffffffffu, tmax, 1));
            tmax = fmaxf(tmax, __shfl_xor_sync(0xffffffffu, tmax, 2));
            tmax = fmaxf(tmax, __shfl_xor_sync(0xffffffffu, tmax, 4));
            tmax = fmaxf(tmax, __shfl_xor_sync(0xffffffffu, tmax, 8));
            float mnew = fmaxf(m[i], tmax);
            float alpha = __expf(m[i] - mnew);
            float psum = 0.f;
#pragma unroll
            for (int j = 0; j < 4; j++) {
                float p = __expf(s[i][j] - mnew);
                s[i][j] = p;
                psum += p;
            }
            psum += __shfl_xor_sync(0xffffffffu, psum, 1);
            psum += __shfl_xor_sync(0xffffffffu, psum, 2);
            psum += __shfl_xor_sync(0xffffffffu, psum, 4);
            psum += __shfl_xor_sync(0xffffffffu, psum, 8);
            l[i] = l[i] * alpha + psum;
            m[i] = mnew;
#pragma unroll
            for (int j = 0; j < 4; j++) o[i][j] *= alpha;
#pragma unroll
            for (int j = 0; j < 4; j++)
                sP[(4 * tc + j) * SP_S + rows[i]] = s[i][j];
        }
        __syncthreads();

#pragma unroll 4
        for (int c = 0; c < FA_BN; c++) {
            float a[8], bv[4];
            *(float4*)(a)     = *(const float4*)&sP[c * SP_S + 4 * tr];
            *(float4*)(a + 4) = *(const float4*)&sP[c * SP_S + 64 + 4 * tr];
            *(float4*)(bv)    = *(const float4*)&sV[c * SV_S + 4 * tc];
#pragma unroll
            for (int i = 0; i < 8; i++)
#pragma unroll
                for (int j = 0; j < 4; j++)
                    o[i][j] += a[i] * bv[j];
        }
    }

#pragma unroll
    for (int i = 0; i < 8; i++) {
        float inv = 1.0f / l[i];
        int t = i0 + rows[i];
        float4 v = make_float4(o[i][0] * inv, o[i][1] * inv,
                               o[i][2] * inv, o[i][3] * inv);
        *(float4*)(g_attn + (size_t)(b * TT + t) * DD + h * DH + 4 * tc) = v;
    }
}

// ---------------------------------------------------------------------------
extern "C" void kernel_launch(void* const* d_in, const int* in_sizes, int n_in,
                              void* d_out, int out_size)
{
    const float* x     = (const float*)d_in[0];
    const float* w_qkv = (const float*)d_in[1];
    const float* b_qkv = (const float*)d_in[2];
    const float* w_out = (const float*)d_in[3];
    const float* b_out = (const float*)d_in[4];
    float* out = (float*)d_out;

    cudaFuncSetAttribute(gemm_mma_kernel,
                         cudaFuncAttributeMaxDynamicSharedMemorySize, GEMM_SMEM);
    cudaFuncSetAttribute(flash_attn_kernel,
                         cudaFuncAttributeMaxDynamicSharedMemorySize, FA_SMEM_BYTES);

    __nv_bfloat16 *xh, *xl, *wqh, *wql, *woh, *wol, *ah, *al;
    float *qkv, *attn;
    cudaGetSymbolAddress((void**)&xh,  g_x_hi);
    cudaGetSymbolAddress((void**)&xl,  g_x_lo);
    cudaGetSymbolAddress((void**)&wqh, g_wq_hi);
    cudaGetSymbolAddress((void**)&wql, g_wq_lo);
    cudaGetSymbolAddress((void**)&woh, g_wo_hi);
    cudaGetSymbolAddress((void**)&wol, g_wo_lo);
    cudaGetSymbolAddress((void**)&ah,  g_a_hi);
    cudaGetSymbolAddress((void**)&al,  g_a_lo);
    cudaGetSymbolAddress((void**)&qkv,  g_qkv);
    cudaGetSymbolAddress((void**)&attn, g_attn);

    // 1. Split x into bf16 hi/lo
    split_kernel<<<(MROWS * DD / 4 + 255) / 256, 256>>>(x, xh, xl, MROWS * DD / 4);
    // 2. Transpose+split weights: [K,N] -> [N,K]
    transpose_split_kernel<<<dim3(QKV_N / 32, DD / 32), 256>>>(w_qkv, wqh, wql, DD, QKV_N);
    transpose_split_kernel<<<dim3(DD / 32, DD / 32), 256>>>(w_out, woh, wol, DD, DD);
    // 3. QKV projection (mma.sync bf16-split)
    gemm_mma_kernel<<<dim3(QKV_N / 128, MROWS / 128), 256, GEMM_SMEM>>>(
        xh, xl, wqh, wql, b_qkv, qkv, QKV_N);
    // 4. Flash attention (fp32)
    flash_attn_kernel<<<dim3(TT / FA_BM, BB * HH), 256, FA_SMEM_BYTES>>>();
    // 5. Split attention output
    split_kernel<<<(MROWS * DD / 4 + 255) / 256, 256>>>(attn, ah, al, MROWS * DD / 4);
    // 6. Output projection (mma.sync bf16-split)
    gemm_mma_kernel<<<dim3(DD / 128, MROWS / 128), 256, GEMM_SMEM>>>(
        ah, al, woh, wol, b_out, out, DD);
}

// round 4
// speedup vs baseline: 2.3995x; 1.7788x over previous
#include <cuda_runtime.h>
#include <cuda_bf16.h>
#include <math.h>
#include <stdint.h>

// Problem constants
constexpr int BB = 2;
constexpr int TT = 2048;
constexpr int DD = 1024;
constexpr int HH = 16;
constexpr int DH = 64;
constexpr int MROWS = BB * TT;          // 4096
constexpr int QKV_N = 3 * DD;           // 3072

// ---------------------------------------------------------------------------
// Scratch (static device allocations)
// ---------------------------------------------------------------------------
__device__ __nv_bfloat16 g_x_hi[MROWS * DD],  g_x_lo[MROWS * DD];
__device__ __nv_bfloat16 g_wq_hi[QKV_N * DD], g_wq_lo[QKV_N * DD];   // w_qkv^T [N,K]
__device__ __nv_bfloat16 g_wo_hi[DD * DD],    g_wo_lo[DD * DD];      // w_out^T [N,K]
// Q/K/V split, layout [(b*16+h)][T][64]
__device__ __nv_bfloat16 g_qh[BB*HH*TT*DH], g_ql[BB*HH*TT*DH];
__device__ __nv_bfloat16 g_kh[BB*HH*TT*DH], g_kl[BB*HH*TT*DH];
__device__ __nv_bfloat16 g_vh[BB*HH*TT*DH], g_vl[BB*HH*TT*DH];
// attention output split, layout [b*T+t][h*64+dh]
__device__ __nv_bfloat16 g_a_hi[MROWS * DD], g_a_lo[MROWS * DD];

// ---------------------------------------------------------------------------
// PTX helpers (sm_80-era, valid at target sm_103)
// ---------------------------------------------------------------------------
__device__ __forceinline__ uint32_t smem_u32(const void* p) {
    return (uint32_t)__cvta_generic_to_shared((void*)p);
}
__device__ __forceinline__ void cp16(uint32_t dst, const void* src) {
    asm volatile("cp.async.cg.shared.global [%0], [%1], 16;" :: "r"(dst), "l"(src));
}
__device__ __forceinline__ void ldsm4(uint32_t* r, uint32_t addr) {
    asm volatile("ldmatrix.sync.aligned.m8n8.x4.shared.b16 {%0,%1,%2,%3}, [%4];"
                 : "=r"(r[0]), "=r"(r[1]), "=r"(r[2]), "=r"(r[3]) : "r"(addr));
}
__device__ __forceinline__ void ldsm4t(uint32_t* r, uint32_t addr) {
    asm volatile("ldmatrix.sync.aligned.m8n8.x4.trans.shared.b16 {%0,%1,%2,%3}, [%4];"
                 : "=r"(r[0]), "=r"(r[1]), "=r"(r[2]), "=r"(r[3]) : "r"(addr));
}
__device__ __forceinline__ void mma_bf16(float* d, const uint32_t* a,
                                         uint32_t b0, uint32_t b1) {
    asm volatile(
        "mma.sync.aligned.m16n8k16.row.col.f32.bf16.bf16.f32 "
        "{%0,%1,%2,%3}, {%4,%5,%6,%7}, {%8,%9}, {%0,%1,%2,%3};"
        : "+f"(d[0]), "+f"(d[1]), "+f"(d[2]), "+f"(d[3])
        : "r"(a[0]), "r"(a[1]), "r"(a[2]), "r"(a[3]), "r"(b0), "r"(b1));
}

// FFMA-only exp (no MUFU). Valid for x <= ~0; clamps below -80.
__device__ __forceinline__ float fast_exp(float x) {
    x = fmaxf(x, -80.f);
    float t = x * 1.44269504f;
    float r = t + 12582912.f;                       // round-to-nearest int
    int   n = __float_as_int(r) - 0x4B400000;
    float f = t - (r - 12582912.f);                 // f in [-0.5, 0.5]
    float u = f * 0.69314718f;
    float p = 1.f + u * (1.f + u * (0.5f + u * (0.16666667f +
              u * (0.041666667f + u * 0.0083333333f))));
    return __int_as_float(__float_as_int(p) + (n << 23));
}

__device__ __forceinline__ void split2(float x, float y, uint32_t& hi, uint32_t& lo) {
    __nv_bfloat16 hx = __float2bfloat16(x), hy = __float2bfloat16(y);
    __nv_bfloat16 lx = __float2bfloat16(x - __bfloat162float(hx));
    __nv_bfloat16 ly = __float2bfloat16(y - __bfloat162float(hy));
    __nv_bfloat162 H(hx, hy), L(lx, ly);
    hi = *(uint32_t*)&H; lo = *(uint32_t*)&L;
}

// ---------------------------------------------------------------------------
// Split conversions
// ---------------------------------------------------------------------------
__global__ __launch_bounds__(256) void split_kernel(
    const float* __restrict__ in, __nv_bfloat16* __restrict__ hi,
    __nv_bfloat16* __restrict__ lo, int n4)
{
    int i = blockIdx.x * blockDim.x + threadIdx.x;
    if (i >= n4) return;
    float4 v = ((const float4*)in)[i];
    uint32_t h0, l0, h1, l1;
    split2(v.x, v.y, h0, l0);
    split2(v.z, v.w, h1, l1);
    ((uint32_t*)hi)[2 * i] = h0; ((uint32_t*)hi)[2 * i + 1] = h1;
    ((uint32_t*)lo)[2 * i] = l0; ((uint32_t*)lo)[2 * i + 1] = l1;
}

__global__ __launch_bounds__(256) void transpose_split_kernel(
    const float* __restrict__ in, __nv_bfloat16* __restrict__ hi,
    __nv_bfloat16* __restrict__ lo, int K, int N)
{
    __shared__ float tile[32][33];
    int n0 = blockIdx.x * 32, k0 = blockIdx.y * 32;
    int tx = threadIdx.x & 31, ty = threadIdx.x >> 5;
#pragma unroll
    for (int j = 0; j < 32; j += 8)
        tile[ty + j][tx] = in[(size_t)(k0 + ty + j) * N + n0 + tx];
    __syncthreads();
#pragma unroll
    for (int j = 0; j < 32; j += 8) {
        float v = tile[tx][ty + j];
        __nv_bfloat16 h = __float2bfloat16(v);
        __nv_bfloat16 l = __float2bfloat16(v - __bfloat162float(h));
        size_t o = (size_t)(n0 + ty + j) * K + k0 + tx;
        hi[o] = h;
        lo[o] = l;
    }
}

// ---------------------------------------------------------------------------
// mma.sync bf16-split GEMM. mode 0: C = A@B^T + bias (fp32 out)
//                           mode 1: QKV — split-write to g_q/k/v h/l, Q scaled
// ---------------------------------------------------------------------------
constexpr int GK = 32;
constexpr int NCHUNK_G = DD / GK;       // 32
constexpr int ROW_B = 80;               // smem row stride bytes (40 bf16)
constexpr int TILE_SM = 128 * ROW_B;    // 10240
constexpr int STAGE_SM = 4 * TILE_SM;   // 40960
constexpr int GEMM_SMEM = 2 * STAGE_SM; // 81920

__global__ __launch_bounds__(256, 1) void gemm_mma_kernel(
    const __nv_bfloat16* __restrict__ Ahi, const __nv_bfloat16* __restrict__ Alo,
    const __nv_bfloat16* __restrict__ Bhi, const __nv_bfloat16* __restrict__ Blo,
    const float* __restrict__ bias, float* __restrict__ C, int N, int mode)
{
    extern __shared__ char sm[];
    const uint32_t smb = smem_u32(sm);
    const int tid = threadIdx.x;
    const int wid = tid >> 5, lane = tid & 31;
    const int wm = wid >> 1, wn = wid & 1;
    const int m0 = blockIdx.y * 128;
    const int n0 = blockIdx.x * 128;

    const char* Ahp = (const char*)Ahi + (size_t)m0 * DD * 2;
    const char* Alp = (const char*)Alo + (size_t)m0 * DD * 2;
    const char* Bhp = (const char*)Bhi + (size_t)n0 * DD * 2;
    const char* Blp = (const char*)Blo + (size_t)n0 * DD * 2;

    const int r_ld[2]  = { (0 * 256 + tid) >> 2, (1 * 256 + tid) >> 2 };
    const int c4_ld[2] = { (0 * 256 + tid) & 3,  (1 * 256 + tid) & 3 };

    auto load_stage = [&](int c, int s) {
        const int k0b = c * GK * 2;
        const uint32_t sb = smb + s * STAGE_SM;
#pragma unroll
        for (int i = 0; i < 2; ++i) {
            const int r = r_ld[i], c4 = c4_ld[i];
            const size_t g = (size_t)r * (DD * 2) + k0b + c4 * 16;
            const uint32_t so = r * ROW_B + c4 * 16;
            cp16(sb + so,               Ahp + g);
            cp16(sb + TILE_SM + so,     Alp + g);
            cp16(sb + 2 * TILE_SM + so, Bhp + g);
            cp16(sb + 3 * TILE_SM + so, Blp + g);
        }
        asm volatile("cp.async.commit_group;" ::: "memory");
    };

    float acc[2][8][4];
#pragma unroll
    for (int mt = 0; mt < 2; ++mt)
#pragma unroll
        for (int nt = 0; nt < 8; ++nt)
#pragma unroll
            for (int j = 0; j < 4; ++j) acc[mt][nt][j] = 0.f;

    const int a_row = wm * 32 + (lane & 15);
    const int a_kb  = (lane >> 4) * 16;
    const int b_row = wn * 64 + (lane & 7) + ((lane >> 4) << 3);
    const int b_kb  = ((lane >> 3) & 1) * 16;

    load_stage(0, 0);

    for (int c = 0; c < NCHUNK_G; ++c) {
        if (c + 1 < NCHUNK_G) {
            load_stage(c + 1, (c + 1) & 1);
            asm volatile("cp.async.wait_group 1;" ::: "memory");
        } else {
            asm volatile("cp.async.wait_group 0;" ::: "memory");
        }
        __syncthreads();

        const uint32_t sb = smb + (c & 1) * STAGE_SM;
#pragma unroll
        for (int k16 = 0; k16 < 2; ++k16) {
            const int kb = k16 * 32;
            uint32_t ah[2][4], al[2][4], bh[4][4], bl[4][4];
#pragma unroll
            for (int mt = 0; mt < 2; ++mt) {
                uint32_t addr = sb + (a_row + mt * 16) * ROW_B + kb + a_kb;
                ldsm4(ah[mt], addr);
                ldsm4(al[mt], addr + TILE_SM);
            }
#pragma unroll
            for (int p = 0; p < 4; ++p) {
                uint32_t addr = sb + 2 * TILE_SM +
                                (b_row + p * 16) * ROW_B + kb + b_kb;
                ldsm4(bh[p], addr);
                ldsm4(bl[p], addr + TILE_SM);
            }
#pragma unroll
            for (int mt = 0; mt < 2; ++mt)
#pragma unroll
                for (int nt = 0; nt < 8; ++nt) {
                    const int p = nt >> 1, h = (nt & 1) * 2;
                    mma_bf16(acc[mt][nt], ah[mt], bh[p][h], bh[p][h + 1]);
                    mma_bf16(acc[mt][nt], ah[mt], bl[p][h], bl[p][h + 1]);
                    mma_bf16(acc[mt][nt], al[mt], bh[p][h], bh[p][h + 1]);
                }
        }
        __syncthreads();
    }

    if (mode == 0) {
#pragma unroll
        for (int mt = 0; mt < 2; ++mt) {
            const int r0 = m0 + wm * 32 + mt * 16 + (lane >> 2);
#pragma unroll
            for (int nt = 0; nt < 8; ++nt) {
                const int cc = n0 + wn * 64 + nt * 8 + (lane & 3) * 2;
                const float2 b2 = *(const float2*)(bias + cc);
                *(float2*)(C + (size_t)r0 * N + cc) =
                    make_float2(acc[mt][nt][0] + b2.x, acc[mt][nt][1] + b2.y);
                *(float2*)(C + (size_t)(r0 + 8) * N + cc) =
                    make_float2(acc[mt][nt][2] + b2.x, acc[mt][nt][3] + b2.y);
            }
        }
    } else {
        // QKV epilogue: split-write to q/k/v, scale Q by 0.125
        const int which = n0 >> 10;   // constant per CTA (128-tile inside 1024)
        __nv_bfloat16* hp = (which == 0) ? g_qh : (which == 1) ? g_kh : g_vh;
        __nv_bfloat16* lp = (which == 0) ? g_ql : (which == 1) ? g_kl : g_vl;
        const float sc = (which == 0) ? 0.125f : 1.f;
#pragma unroll
        for (int mt = 0; mt < 2; ++mt) {
            const int r0 = m0 + wm * 32 + mt * 16 + (lane >> 2);
#pragma unroll
            for (int nt = 0; nt < 8; ++nt) {
                const int cc = n0 + wn * 64 + nt * 8 + (lane & 3) * 2;
                const int h = (cc & 1023) >> 6, dh = cc & 63;
                const float2 b2 = *(const float2*)(bias + cc);
#pragma unroll
                for (int half = 0; half < 2; ++half) {
                    const int r = r0 + half * 8;
                    const int bq = r >> 11, tq = r & 2047;
                    const size_t off = ((size_t)(bq * 16 + h) * 2048 + tq) * 64 + dh;
                    uint32_t hv, lv;
                    split2((acc[mt][nt][2 * half] + b2.x) * sc,
                           (acc[mt][nt][2 * half + 1] + b2.y) * sc, hv, lv);
                    *(uint32_t*)(hp + off) = hv;
                    *(uint32_t*)(lp + off) = lv;
                }
            }
        }
    }
}

// ---------------------------------------------------------------------------
// Tensor-core flash attention, causal, bf16-split (3-pass QK and PV).
// CTA: 128 q rows of one (b,h), 8 warps (warp = 16 q rows), KV tiles of 64.
// smem: Qh|Ql [128][72] + 2 stages of {Kh,Kl,Vh,Vl}[64][72] (stride 144B).
// ---------------------------------------------------------------------------
constexpr int AT_Q_OFF   = 0;           // Qh 18432, Ql 18432
constexpr int AT_STG_OFF = 36864;
constexpr int AT_ARR     = 9216;        // 64*144
constexpr int AT_STG     = 4 * AT_ARR;  // 36864
constexpr int AT_SMEM    = AT_STG_OFF + 2 * AT_STG;  // 110592

__global__ __launch_bounds__(256, 1) void flash_attn_tc_kernel()
{
    extern __shared__ char sm[];
    const uint32_t smb = smem_u32(sm);
    const int tid = threadIdx.x, wid = tid >> 5, lane = tid & 31;
    const int bx = (int)gridDim.x - 1 - (int)blockIdx.x;  // heavy blocks first
    const int i0 = bx * 128;
    const int ntile = 2 * bx + 2;
    const int bh = blockIdx.y;
    const size_t head2 = (size_t)bh * TT * DH * 2;       // byte offset

    const char* qh_g = (const char*)g_qh + head2 + (size_t)i0 * DH * 2;
    const char* ql_g = (const char*)g_ql + head2 + (size_t)i0 * DH * 2;
    const char* kh_g = (const char*)g_kh + head2;
    const char* kl_g = (const char*)g_kl + head2;
    const char* vh_g = (const char*)g_vh + head2;
    const char* vl_g = (const char*)g_vl + head2;

    // Q tile: 128 rows x 128B
#pragma unroll
    for (int it = 0; it < 4; ++it) {
        int cid = it * 256 + tid;
        int row = cid >> 3, c = cid & 7;
        cp16(smb + AT_Q_OFF + row * 144 + c * 16,        qh_g + row * 128 + c * 16);
        cp16(smb + AT_Q_OFF + 18432 + row * 144 + c * 16, ql_g + row * 128 + c * 16);
    }
    asm volatile("cp.async.commit_group;" ::: "memory");

    auto load_kv = [&](int t, int s) {
        const uint32_t sb = smb + AT_STG_OFF + s * AT_STG;
        const int j0b = t * 64 * 128;
#pragma unroll
        for (int it = 0; it < 2; ++it) {
            int cid = it * 256 + tid;
            int row = cid >> 3, c = cid & 7;
            uint32_t so = row * 144 + c * 16;
            int go = j0b + row * 128 + c * 16;
            cp16(sb + so,              kh_g + go);
            cp16(sb + AT_ARR + so,     kl_g + go);
            cp16(sb + 2 * AT_ARR + so, vh_g + go);
            cp16(sb + 3 * AT_ARR + so, vl_g + go);
        }
        asm volatile("cp.async.commit_group;" ::: "memory");
    };
    load_kv(0, 0);

    // Q fragments (held in registers for the whole pass)
    asm volatile("cp.async.wait_group 1;" ::: "memory");
    __syncthreads();
    uint32_t qh_f[4][4], ql_f[4][4];
    {
        const uint32_t a_off = (wid * 16 + (lane & 15)) * 144 + (lane >> 4) * 16;
#pragma unroll
        for (int kc = 0; kc < 4; ++kc) {
            ldsm4(qh_f[kc], smb + AT_Q_OFF + a_off + kc * 32);
            ldsm4(ql_f[kc], smb + AT_Q_OFF + 18432 + a_off + kc * 32);
        }
    }

    float oacc[8][4];
#pragma unroll
    for (int nt = 0; nt < 8; ++nt)
#pragma unroll
        for (int j = 0; j < 4; ++j) oacc[nt][j] = 0.f;
    float mrow[2] = {-1e30f, -1e30f}, lrow[2] = {0.f, 0.f};

    const uint32_t kb_off = ((lane & 7) + ((lane >> 4) << 3)) * 144 +
                            ((lane >> 3) & 1) * 16;
    const uint32_t vrow = (lane & 7) + (((lane >> 3) & 1) << 3);
    const uint32_t vcol = (lane >> 4) * 16;

    for (int t = 0; t < ntile; ++t) {
        if (t + 1 < ntile) {
            load_kv(t + 1, (t + 1) & 1);
            asm volatile("cp.async.wait_group 1;" ::: "memory");
        } else {
            asm volatile("cp.async.wait_group 0;" ::: "memory");
        }
        __syncthreads();
        const uint32_t sb = smb + AT_STG_OFF + (t & 1) * AT_STG;
        const int j0 = t * 64;

        // S = Q @ K^T (3-pass split)
        float sacc[8][4];
#pragma unroll
        for (int nt = 0; nt < 8; ++nt)
#pragma unroll
            for (int j = 0; j < 4; ++j) sacc[nt][j] = 0.f;

#pragma unroll
        for (int kc = 0; kc < 4; ++kc) {
#pragma unroll
            for (int p = 0; p < 4; ++p) {
                uint32_t kh4[4], kl4[4];
                uint32_t addr = sb + kb_off + p * (16 * 144) + kc * 32;
                ldsm4(kh4, addr);
                ldsm4(kl4, addr + AT_ARR);
                mma_bf16(sacc[2 * p],     qh_f[kc], kh4[0], kh4[1]);
                mma_bf16(sacc[2 * p],     qh_f[kc], kl4[0], kl4[1]);
                mma_bf16(sacc[2 * p],     ql_f[kc], kh4[0], kh4[1]);
                mma_bf16(sacc[2 * p + 1], qh_f[kc], kh4[2], kh4[3]);
                mma_bf16(sacc[2 * p + 1], qh_f[kc], kl4[2], kl4[3]);
                mma_bf16(sacc[2 * p + 1], ql_f[kc], kh4[2], kh4[3]);
            }
        }

        // causal mask (only on tiles that can cross the diagonal)
        if (j0 + 63 > i0 + wid * 16) {
#pragma unroll
            for (int i = 0; i < 2; ++i) {
                const int qi = i0 + wid * 16 + (lane >> 2) + 8 * i;
#pragma unroll
                for (int nt = 0; nt < 8; ++nt) {
                    const int kt0 = j0 + nt * 8 + (lane & 3) * 2;
                    if (kt0 > qi)     sacc[nt][2 * i]     = -1e30f;
                    if (kt0 + 1 > qi) sacc[nt][2 * i + 1] = -1e30f;
                }
            }
        }

        // online softmax (FFMA-only exp) + O rescale
#pragma unroll
        for (int i = 0; i < 2; ++i) {
            float mx = -1e30f;
#pragma unroll
            for (int nt = 0; nt < 8; ++nt)
                mx = fmaxf(mx, fmaxf(sacc[nt][2 * i], sacc[nt][2 * i + 1]));
            mx = fmaxf(mx, __shfl_xor_sync(0xffffffffu, mx, 1));
            mx = fmaxf(mx, __shfl_xor_sync(0xffffffffu, mx, 2));
            const float mn = fmaxf(mrow[i], mx);
            const float al = fast_exp(mrow[i] - mn);
            mrow[i] = mn;
            float sum = 0.f;
#pragma unroll
            for (int nt = 0; nt < 8; ++nt) {
                float p0 = fast_exp(sacc[nt][2 * i] - mn);
                float p1 = fast_exp(sacc[nt][2 * i + 1] - mn);
                sacc[nt][2 * i] = p0;
                sacc[nt][2 * i + 1] = p1;
                sum += p0 + p1;
            }
            sum += __shfl_xor_sync(0xffffffffu, sum, 1);
            sum += __shfl_xor_sync(0xffffffffu, sum, 2);
            lrow[i] = lrow[i] * al + sum;
#pragma unroll
            for (int nt = 0; nt < 8; ++nt) {
                oacc[nt][2 * i] *= al;
                oacc[nt][2 * i + 1] *= al;
            }
        }

        // pack P into A-fragments (hi/lo)
        uint32_t pah[4][4], pal[4][4];
#pragma unroll
        for (int kt = 0; kt < 4; ++kt) {
            split2(sacc[2 * kt][0],     sacc[2 * kt][1],     pah[kt][0], pal[kt][0]);
            split2(sacc[2 * kt][2],     sacc[2 * kt][3],     pah[kt][1], pal[kt][1]);
            split2(sacc[2 * kt + 1][0], sacc[2 * kt + 1][1], pah[kt][2], pal[kt][2]);
            split2(sacc[2 * kt + 1][2], sacc[2 * kt + 1][3], pah[kt][3], pal[kt][3]);
        }

        // O += P @ V (3-pass split), V fragments via ldmatrix.trans
#pragma unroll
        for (int kt = 0; kt < 4; ++kt) {
#pragma unroll
            for (int vd = 0; vd < 4; ++vd) {
                uint32_t vh4[4], vl4[4];
                uint32_t addr = sb + 2 * AT_ARR + (kt * 16 + vrow) * 144 +
                                vcol + vd * 32;
                ldsm4t(vh4, addr);
                ldsm4t(vl4, addr + AT_ARR);
                mma_bf16(oacc[2 * vd],     pah[kt], vh4[0], vh4[1]);
                mma_bf16(oacc[2 * vd],     pal[kt], vh4[0], vh4[1]);
                mma_bf16(oacc[2 * vd],     pah[kt], vl4[0], vl4[1]);
                mma_bf16(oacc[2 * vd + 1], pah[kt], vh4[2], vh4[3]);
                mma_bf16(oacc[2 * vd + 1], pal[kt], vh4[2], vh4[3]);
                mma_bf16(oacc[2 * vd + 1], pah[kt], vl4[2], vl4[3]);
            }
        }
        __syncthreads();
    }

    // epilogue: normalize, split-write to g_a_hi/lo [b*T+t][h*64+dh]
    const int b = bh >> 4, h = bh & 15;
#pragma unroll
    for (int i = 0; i < 2; ++i) {
        const float inv = 1.0f / lrow[i];
        const int trow = i0 + wid * 16 + (lane >> 2) + 8 * i;
        const size_t rbase = (size_t)(b * TT + trow) * DD + h * 64;
#pragma unroll
        for (int nt = 0; nt < 8; ++nt) {
            const int col = nt * 8 + (lane & 3) * 2;
            uint32_t hv, lv;
            split2(oacc[nt][2 * i] * inv, oacc[nt][2 * i + 1] * inv, hv, lv);
            *(uint32_t*)(g_a_hi + rbase + col) = hv;
            *(uint32_t*)(g_a_lo + rbase + col) = lv;
        }
    }
}

// ---------------------------------------------------------------------------
extern "C" void kernel_launch(void* const* d_in, const int* in_sizes, int n_in,
                              void* d_out, int out_size)
{
    const float* x     = (const float*)d_in[0];
    const float* w_qkv = (const float*)d_in[1];
    const float* b_qkv = (const float*)d_in[2];
    const float* w_out = (const float*)d_in[3];
    const float* b_out = (const float*)d_in[4];
    float* out = (float*)d_out;

    cudaFuncSetAttribute(gemm_mma_kernel,
                         cudaFuncAttributeMaxDynamicSharedMemorySize, GEMM_SMEM);
    cudaFuncSetAttribute(flash_attn_tc_kernel,
                         cudaFuncAttributeMaxDynamicSharedMemorySize, AT_SMEM);

    __nv_bfloat16 *xh, *xl, *wqh, *wql, *woh, *wol, *ah, *al;
    cudaGetSymbolAddress((void**)&xh,  g_x_hi);
    cudaGetSymbolAddress((void**)&xl,  g_x_lo);
    cudaGetSymbolAddress((void**)&wqh, g_wq_hi);
    cudaGetSymbolAddress((void**)&wql, g_wq_lo);
    cudaGetSymbolAddress((void**)&woh, g_wo_hi);
    cudaGetSymbolAddress((void**)&wol, g_wo_lo);
    cudaGetSymbolAddress((void**)&ah,  g_a_hi);
    cudaGetSymbolAddress((void**)&al,  g_a_lo);

    // 1. Split x
    split_kernel<<<(MROWS * DD / 4 + 255) / 256, 256>>>(x, xh, xl, MROWS * DD / 4);
    // 2. Transpose+split weights
    transpose_split_kernel<<<dim3(QKV_N / 32, DD / 32), 256>>>(w_qkv, wqh, wql, DD, QKV_N);
    transpose_split_kernel<<<dim3(DD / 32, DD / 32), 256>>>(w_out, woh, wol, DD, DD);
    // 3. QKV projection -> split q/k/v directly (Q pre-scaled)
    gemm_mma_kernel<<<dim3(QKV_N / 128, MROWS / 128), 256, GEMM_SMEM>>>(
        xh, xl, wqh, wql, b_qkv, nullptr, QKV_N, 1);
    // 4. Tensor-core flash attention -> split attn output directly
    flash_attn_tc_kernel<<<dim3(TT / 128, BB * HH), 256, AT_SMEM>>>();
    // 5. Output projection (fp32 out)
    gemm_mma_kernel<<<dim3(DD / 128, MROWS / 128), 256, GEMM_SMEM>>>(
        ah, al, woh, wol, b_out, out, DD, 0);
}

// round 6
// speedup vs baseline: 3.5730x; 1.4890x over previous
#include <cuda_runtime.h>
#include <cuda_fp16.h>
#include <math.h>
#include <stdint.h>

// Problem constants
constexpr int BB = 2;
constexpr int TT = 2048;
constexpr int DD = 1024;
constexpr int HH = 16;
constexpr int DH = 64;
constexpr int MROWS = BB * TT;          // 4096
constexpr int QKV_N = 3 * DD;           // 3072

// ---------------------------------------------------------------------------
// Scratch (static device allocations)
// ---------------------------------------------------------------------------
__device__ __half g_x_hi[MROWS * DD], g_x_lo[MROWS * DD];
__device__ __half g_wq[QKV_N * DD];            // w_qkv^T [N,K] fp16
__device__ __half g_wo[DD * DD];               // w_out^T [N,K] fp16
// layout [(b*16+h)][T][64]
__device__ __half g_qh[BB*HH*TT*DH], g_ql[BB*HH*TT*DH];
__device__ __half g_k [BB*HH*TT*DH];
__device__ __half g_vh[BB*HH*TT*DH], g_vl[BB*HH*TT*DH];
// attention output split, layout [b*T+t][h*64+dh]
__device__ __half g_a_hi[MROWS * DD], g_a_lo[MROWS * DD];

// ---------------------------------------------------------------------------
// PTX helpers
// ---------------------------------------------------------------------------
__device__ __forceinline__ uint32_t smem_u32(const void* p) {
    return (uint32_t)__cvta_generic_to_shared((void*)p);
}
__device__ __forceinline__ void cp16(uint32_t dst, const void* src) {
    asm volatile("cp.async.cg.shared.global [%0], [%1], 16;" :: "r"(dst), "l"(src));
}
__device__ __forceinline__ void ldsm4(uint32_t* r, uint32_t addr) {
    asm volatile("ldmatrix.sync.aligned.m8n8.x4.shared.b16 {%0,%1,%2,%3}, [%4];"
                 : "=r"(r[0]), "=r"(r[1]), "=r"(r[2]), "=r"(r[3]) : "r"(addr));
}
__device__ __forceinline__ void ldsm4t(uint32_t* r, uint32_t addr) {
    asm volatile("ldmatrix.sync.aligned.m8n8.x4.trans.shared.b16 {%0,%1,%2,%3}, [%4];"
                 : "=r"(r[0]), "=r"(r[1]), "=r"(r[2]), "=r"(r[3]) : "r"(addr));
}
__device__ __forceinline__ void mma_f16(float* d, const uint32_t* a,
                                        uint32_t b0, uint32_t b1) {
    asm volatile(
        "mma.sync.aligned.m16n8k16.row.col.f32.f16.f16.f32 "
        "{%0,%1,%2,%3}, {%4,%5,%6,%7}, {%8,%9}, {%0,%1,%2,%3};"
        : "+f"(d[0]), "+f"(d[1]), "+f"(d[2]), "+f"(d[3])
        : "r"(a[0]), "r"(a[1]), "r"(a[2]), "r"(a[3]), "r"(b0), "r"(b1));
}

// FFMA-only exp (no MUFU)
__device__ __forceinline__ float fast_exp(float x) {
    x = fmaxf(x, -80.f);
    float t = x * 1.44269504f;
    float r = t + 12582912.f;
    int   n = __float_as_int(r) - 0x4B400000;
    float f = t - (r - 12582912.f);
    float u = f * 0.69314718f;
    float p = 1.f + u * (1.f + u * (0.5f + u * (0.16666667f +
              u * (0.041666667f + u * 0.0083333333f))));
    return __int_as_float(__float_as_int(p) + (n << 23));
}

__device__ __forceinline__ uint32_t h2pack(float x, float y) {
    __half2 h = __floats2half2_rn(x, y);
    return *(uint32_t*)&h;
}
__device__ __forceinline__ void split2h(float x, float y, uint32_t& hi, uint32_t& lo) {
    __half hx = __float2half_rn(x), hy = __float2half_rn(y);
    __half lx = __float2half_rn(x - __half2float(hx));
    __half ly = __float2half_rn(y - __half2float(hy));
    __half2 H(hx, hy), L(lx, ly);
    hi = *(uint32_t*)&H; lo = *(uint32_t*)&L;
}

// ---------------------------------------------------------------------------
// Conversions
// ---------------------------------------------------------------------------
__global__ __launch_bounds__(256) void split_kernel(
    const float* __restrict__ in, __half* __restrict__ hi,
    __half* __restrict__ lo, int n4)
{
    int i = blockIdx.x * blockDim.x + threadIdx.x;
    if (i >= n4) return;
    float4 v = ((const float4*)in)[i];
    uint32_t h0, l0, h1, l1;
    split2h(v.x, v.y, h0, l0);
    split2h(v.z, v.w, h1, l1);
    ((uint32_t*)hi)[2 * i] = h0; ((uint32_t*)hi)[2 * i + 1] = h1;
    ((uint32_t*)lo)[2 * i] = l0; ((uint32_t*)lo)[2 * i + 1] = l1;
}

// [K,N] fp32 -> [N,K] fp16 (single)
__global__ __launch_bounds__(256) void transpose_h_kernel(
    const float* __restrict__ in, __half* __restrict__ out, int K, int N)
{
    __shared__ float tile[32][33];
    int n0 = blockIdx.x * 32, k0 = blockIdx.y * 32;
    int tx = threadIdx.x & 31, ty = threadIdx.x >> 5;
#pragma unroll
    for (int j = 0; j < 32; j += 8)
        tile[ty + j][tx] = in[(size_t)(k0 + ty + j) * N + n0 + tx];
    __syncthreads();
#pragma unroll
    for (int j = 0; j < 32; j += 8)
        out[(size_t)(n0 + ty + j) * K + k0 + tx] = __float2half_rn(tile[tx][ty + j]);
}

// ---------------------------------------------------------------------------
// fp16 2-pass GEMM: C = (Ah+Al) @ B^T + bias. A split fp16, B single fp16.
// 128x128 tile, BK=64, 256 threads (8 warps 4x2), 2-stage cp.async.
// smem: 2 stages x {Ah, Al, B}, each 128 rows x 144B (128B data + 16 pad).
// mode 0: fp32 out + bias. mode 1: QKV epilogue (split q, single k, split v).
// ---------------------------------------------------------------------------
constexpr int ROW_B = 144;
constexpr int TILE_SM = 128 * ROW_B;      // 18432
constexpr int STAGE_SM = 3 * TILE_SM;     // 55296
constexpr int GEMM_SMEM = 2 * STAGE_SM;   // 110592
constexpr int NCHUNK_G = DD / 64;         // 16

__global__ __launch_bounds__(256, 1) void gemm_mma_kernel(
    const __half* __restrict__ Ahi, const __half* __restrict__ Alo,
    const __half* __restrict__ Bw, const float* __restrict__ bias,
    float* __restrict__ C, int N, int mode)
{
    extern __shared__ char sm[];
    const uint32_t smb = smem_u32(sm);
    const int tid = threadIdx.x;
    const int wid = tid >> 5, lane = tid & 31;
    const int wm = wid >> 1, wn = wid & 1;
    const int m0 = blockIdx.y * 128;
    const int n0 = blockIdx.x * 128;

    const char* Ahp = (const char*)Ahi + (size_t)m0 * DD * 2;
    const char* Alp = (const char*)Alo + (size_t)m0 * DD * 2;
    const char* Bp  = (const char*)Bw  + (size_t)n0 * DD * 2;

    auto load_stage = [&](int c, int s) {
        const int k0b = c * 128;              // 64 fp16 = 128B per chunk
        const uint32_t sb = smb + s * STAGE_SM;
#pragma unroll
        for (int i = 0; i < 4; ++i) {
            const int cid = i * 256 + tid;    // 0..1023
            const int r = cid >> 3, c8 = (cid & 7) * 16;
            const size_t g = (size_t)r * 2048 + k0b + c8;
            const uint32_t so = r * ROW_B + c8;
            cp16(sb + so,               Ahp + g);
            cp16(sb + TILE_SM + so,     Alp + g);
            cp16(sb + 2 * TILE_SM + so, Bp + g);
        }
        asm volatile("cp.async.commit_group;" ::: "memory");
    };

    float acc[2][8][4];
#pragma unroll
    for (int mt = 0; mt < 2; ++mt)
#pragma unroll
        for (int nt = 0; nt < 8; ++nt)
#pragma unroll
            for (int j = 0; j < 4; ++j) acc[mt][nt][j] = 0.f;

    const int a_row = wm * 32 + (lane & 15);
    const int a_kb  = (lane >> 4) * 16;
    const int b_row = wn * 64 + (lane & 7) + ((lane >> 4) << 3);
    const int b_kb  = ((lane >> 3) & 1) * 16;

    load_stage(0, 0);

    for (int c = 0; c < NCHUNK_G; ++c) {
        if (c + 1 < NCHUNK_G) {
            load_stage(c + 1, (c + 1) & 1);
            asm volatile("cp.async.wait_group 1;" ::: "memory");
        } else {
            asm volatile("cp.async.wait_group 0;" ::: "memory");
        }
        __syncthreads();

        const uint32_t sb = smb + (c & 1) * STAGE_SM;
#pragma unroll
        for (int k16 = 0; k16 < 4; ++k16) {
            const int kb = k16 * 32;
            uint32_t ah[2][4], al[2][4], bw[4][4];
#pragma unroll
            for (int mt = 0; mt < 2; ++mt) {
                uint32_t addr = sb + (a_row + mt * 16) * ROW_B + kb + a_kb;
                ldsm4(ah[mt], addr);
                ldsm4(al[mt], addr + TILE_SM);
            }
#pragma unroll
            for (int p = 0; p < 4; ++p)
                ldsm4(bw[p], sb + 2 * TILE_SM + (b_row + p * 16) * ROW_B + kb + b_kb);
#pragma unroll
            for (int mt = 0; mt < 2; ++mt)
#pragma unroll
                for (int nt = 0; nt < 8; ++nt) {
                    const int p = nt >> 1, h = (nt & 1) * 2;
                    mma_f16(acc[mt][nt], ah[mt], bw[p][h], bw[p][h + 1]);
                    mma_f16(acc[mt][nt], al[mt], bw[p][h], bw[p][h + 1]);
                }
        }
        __syncthreads();
    }

    if (mode == 0) {
#pragma unroll
        for (int mt = 0; mt < 2; ++mt) {
            const int r0 = m0 + wm * 32 + mt * 16 + (lane >> 2);
#pragma unroll
            for (int nt = 0; nt < 8; ++nt) {
                const int cc = n0 + wn * 64 + nt * 8 + (lane & 3) * 2;
                const float2 b2 = *(const float2*)(bias + cc);
                *(float2*)(C + (size_t)r0 * N + cc) =
                    make_float2(acc[mt][nt][0] + b2.x, acc[mt][nt][1] + b2.y);
                *(float2*)(C + (size_t)(r0 + 8) * N + cc) =
                    make_float2(acc[mt][nt][2] + b2.x, acc[mt][nt][3] + b2.y);
            }
        }
    } else {
        // QKV epilogue: q -> split (x0.125), k -> single, v -> split
        const int which = n0 >> 10;
        const float sc = (which == 0) ? 0.125f : 1.f;
#pragma unroll
        for (int mt = 0; mt < 2; ++mt) {
            const int r0 = m0 + wm * 32 + mt * 16 + (lane >> 2);
#pragma unroll
            for (int nt = 0; nt < 8; ++nt) {
                const int cc = n0 + wn * 64 + nt * 8 + (lane & 3) * 2;
                const int h = (cc & 1023) >> 6, dh = cc & 63;
                const float2 b2 = *(const float2*)(bias + cc);
#pragma unroll
                for (int half_i = 0; half_i < 2; ++half_i) {
                    const int r = r0 + half_i * 8;
                    const int bq = r >> 11, tq = r & 2047;
                    const size_t off = ((size_t)(bq * 16 + h) * 2048 + tq) * 64 + dh;
                    const float v0 = (acc[mt][nt][2 * half_i] + b2.x) * sc;
                    const float v1 = (acc[mt][nt][2 * half_i + 1] + b2.y) * sc;
                    if (which == 0) {
                        uint32_t hv, lv;
                        split2h(v0, v1, hv, lv);
                        *(uint32_t*)(g_qh + off) = hv;
                        *(uint32_t*)(g_ql + off) = lv;
                    } else if (which == 1) {
                        *(uint32_t*)(g_k + off) = h2pack(v0, v1);
                    } else {
                        uint32_t hv, lv;
                        split2h(v0, v1, hv, lv);
                        *(uint32_t*)(g_vh + off) = hv;
                        *(uint32_t*)(g_vl + off) = lv;
                    }
                }
            }
        }
    }
}

// ---------------------------------------------------------------------------
// Tensor-core flash attention, causal, fp16.
// QK: Q split (2-pass) x K single. PV: P single x V split (2-pass).
// CTA: 128 q rows, 8 warps (16 rows each), KV tiles of 64, 2-stage cp.async.
// smem: Qh|Ql [128][144B] + 2 stages x {K, Vh, Vl}[64][144B].
// ---------------------------------------------------------------------------
constexpr int AT_QL_OFF  = 18432;
constexpr int AT_STG_OFF = 36864;
constexpr int AT_ARR     = 64 * ROW_B;        // 9216
constexpr int AT_STG     = 3 * AT_ARR;        // 27648
constexpr int AT_SMEM    = AT_STG_OFF + 2 * AT_STG;   // 92160

__global__ __launch_bounds__(256, 1) void flash_attn_tc_kernel()
{
    extern __shared__ char sm[];
    const uint32_t smb = smem_u32(sm);
    const int tid = threadIdx.x, wid = tid >> 5, lane = tid & 31;
    const int bx = (int)gridDim.x - 1 - (int)blockIdx.x;   // heavy blocks first
    const int i0 = bx * 128;
    const int ntile = 2 * bx + 2;
    const int bh = blockIdx.y;
    const size_t head2 = (size_t)bh * TT * DH * 2;

    const char* qh_g = (const char*)g_qh + head2 + (size_t)i0 * DH * 2;
    const char* ql_g = (const char*)g_ql + head2 + (size_t)i0 * DH * 2;
    const char* k_g  = (const char*)g_k  + head2;
    const char* vh_g = (const char*)g_vh + head2;
    const char* vl_g = (const char*)g_vl + head2;

#pragma unroll
    for (int it = 0; it < 4; ++it) {
        int cid = it * 256 + tid;
        int row = cid >> 3, c8 = (cid & 7) * 16;
        cp16(smb + row * ROW_B + c8,             qh_g + row * 128 + c8);
        cp16(smb + AT_QL_OFF + row * ROW_B + c8, ql_g + row * 128 + c8);
    }
    asm volatile("cp.async.commit_group;" ::: "memory");

    auto load_kv = [&](int t, int s) {
        const uint32_t sb = smb + AT_STG_OFF + s * AT_STG;
        const int j0b = t * 64 * 128;
#pragma unroll
        for (int it = 0; it < 2; ++it) {
            int cid = it * 256 + tid;
            int row = cid >> 3, c8 = (cid & 7) * 16;
            uint32_t so = row * ROW_B + c8;
            int go = j0b + row * 128 + c8;
            cp16(sb + so,              k_g + go);
            cp16(sb + AT_ARR + so,     vh_g + go);
            cp16(sb + 2 * AT_ARR + so, vl_g + go);
        }
        asm volatile("cp.async.commit_group;" ::: "memory");
    };
    load_kv(0, 0);

    asm volatile("cp.async.wait_group 1;" ::: "memory");
    __syncthreads();
    uint32_t qh_f[4][4], ql_f[4][4];
    {
        const uint32_t a_off = (wid * 16 + (lane & 15)) * ROW_B + (lane >> 4) * 16;
#pragma unroll
        for (int kc = 0; kc < 4; ++kc) {
            ldsm4(qh_f[kc], smb + a_off + kc * 32);
            ldsm4(ql_f[kc], smb + AT_QL_OFF + a_off + kc * 32);
        }
    }

    float oacc[8][4];
#pragma unroll
    for (int nt = 0; nt < 8; ++nt)
#pragma unroll
        for (int j = 0; j < 4; ++j) oacc[nt][j] = 0.f;
    float mrow[2] = {-1e30f, -1e30f}, lrow[2] = {0.f, 0.f};

    const uint32_t kb_off = ((lane & 7) + ((lane >> 4) << 3)) * ROW_B +
                            ((lane >> 3) & 1) * 16;
    const uint32_t vrow = (lane & 7) + (((lane >> 3) & 1) << 3);
    const uint32_t vcol = (lane >> 4) * 16;

    for (int t = 0; t < ntile; ++t) {
        if (t + 1 < ntile) {
            load_kv(t + 1, (t + 1) & 1);
            asm volatile("cp.async.wait_group 1;" ::: "memory");
        } else {
            asm volatile("cp.async.wait_group 0;" ::: "memory");
        }
        __syncthreads();
        const uint32_t sb = smb + AT_STG_OFF + (t & 1) * AT_STG;
        const int j0 = t * 64;

        // S = Q @ K^T  (Qh + Ql passes)
        float sacc[8][4];
#pragma unroll
        for (int nt = 0; nt < 8; ++nt)
#pragma unroll
            for (int j = 0; j < 4; ++j) sacc[nt][j] = 0.f;

#pragma unroll
        for (int kc = 0; kc < 4; ++kc) {
#pragma unroll
            for (int p = 0; p < 4; ++p) {
                uint32_t kh4[4];
                ldsm4(kh4, sb + kb_off + p * (16 * ROW_B) + kc * 32);
                mma_f16(sacc[2 * p],     qh_f[kc], kh4[0], kh4[1]);
                mma_f16(sacc[2 * p],     ql_f[kc], kh4[0], kh4[1]);
                mma_f16(sacc[2 * p + 1], qh_f[kc], kh4[2], kh4[3]);
                mma_f16(sacc[2 * p + 1], ql_f[kc], kh4[2], kh4[3]);
            }
        }

        // causal mask
        if (j0 + 63 > i0 + wid * 16) {
#pragma unroll
            for (int i = 0; i < 2; ++i) {
                const int qi = i0 + wid * 16 + (lane >> 2) + 8 * i;
#pragma unroll
                for (int nt = 0; nt < 8; ++nt) {
                    const int kt0 = j0 + nt * 8 + (lane & 3) * 2;
                    if (kt0 > qi)     sacc[nt][2 * i]     = -1e30f;
                    if (kt0 + 1 > qi) sacc[nt][2 * i + 1] = -1e30f;
                }
            }
        }

        // online softmax
#pragma unroll
        for (int i = 0; i < 2; ++i) {
            float mx = -1e30f;
#pragma unroll
            for (int nt = 0; nt < 8; ++nt)
                mx = fmaxf(mx, fmaxf(sacc[nt][2 * i], sacc[nt][2 * i + 1]));
            mx = fmaxf(mx, __shfl_xor_sync(0xffffffffu, mx, 1));
            mx = fmaxf(mx, __shfl_xor_sync(0xffffffffu, mx, 2));
            const float mn = fmaxf(mrow[i], mx);
            const float al = fast_exp(mrow[i] - mn);
            mrow[i] = mn;
            float sum = 0.f;
#pragma unroll
            for (int nt = 0; nt < 8; ++nt) {
                float p0 = fast_exp(sacc[nt][2 * i] - mn);
                float p1 = fast_exp(sacc[nt][2 * i + 1] - mn);
                sacc[nt][2 * i] = p0;
                sacc[nt][2 * i + 1] = p1;
                sum += p0 + p1;
            }
            sum += __shfl_xor_sync(0xffffffffu, sum, 1);
            sum += __shfl_xor_sync(0xffffffffu, sum, 2);
            lrow[i] = lrow[i] * al + sum;
#pragma unroll
            for (int nt = 0; nt < 8; ++nt) {
                oacc[nt][2 * i] *= al;
                oacc[nt][2 * i + 1] *= al;
            }
        }

        // O += P @ (Vh + Vl), P single fp16
#pragma unroll
        for (int kt = 0; kt < 4; ++kt) {
            uint32_t pa[4];
            pa[0] = h2pack(sacc[2 * kt][0],     sacc[2 * kt][1]);
            pa[1] = h2pack(sacc[2 * kt][2],     sacc[2 * kt][3]);
            pa[2] = h2pack(sacc[2 * kt + 1][0], sacc[2 * kt + 1][1]);
            pa[3] = h2pack(sacc[2 * kt + 1][2], sacc[2 * kt + 1][3]);
#pragma unroll
            for (int vd = 0; vd < 4; ++vd) {
                uint32_t vh4[4], vl4[4];
                uint32_t addr = sb + AT_ARR + (kt * 16 + vrow) * ROW_B +
                                vcol + vd * 32;
                ldsm4t(vh4, addr);
                ldsm4t(vl4, addr + AT_ARR);
                mma_f16(oacc[2 * vd],     pa, vh4[0], vh4[1]);
                mma_f16(oacc[2 * vd],     pa, vl4[0], vl4[1]);
                mma_f16(oacc[2 * vd + 1], pa, vh4[2], vh4[3]);
                mma_f16(oacc[2 * vd + 1], pa, vl4[2], vl4[3]);
            }
        }
        __syncthreads();
    }

    // epilogue: normalize, split-write [b*T+t][h*64+dh]
    const int b = bh >> 4, h = bh & 15;
#pragma unroll
    for (int i = 0; i < 2; ++i) {
        const float inv = 1.0f / lrow[i];
        const int trow = i0 + wid * 16 + (lane >> 2) + 8 * i;
        const size_t rbase = (size_t)(b * TT + trow) * DD + h * 64;
#pragma unroll
        for (int nt = 0; nt < 8; ++nt) {
            const int col = nt * 8 + (lane & 3) * 2;
            uint32_t hv, lv;
            split2h(oacc[nt][2 * i] * inv, oacc[nt][2 * i + 1] * inv, hv, lv);
            *(uint32_t*)(g_a_hi + rbase + col) = hv;
            *(uint32_t*)(g_a_lo + rbase + col) = lv;
        }
    }
}

// ---------------------------------------------------------------------------
extern "C" void kernel_launch(void* const* d_in, const int* in_sizes, int n_in,
                              void* d_out, int out_size)
{
    const float* x     = (const float*)d_in[0];
    const float* w_qkv = (const float*)d_in[1];
    const float* b_qkv = (const float*)d_in[2];
    const float* w_out = (const float*)d_in[3];
    const float* b_out = (const float*)d_in[4];
    float* out = (float*)d_out;

    cudaFuncSetAttribute(gemm_mma_kernel,
                         cudaFuncAttributeMaxDynamicSharedMemorySize, GEMM_SMEM);
    cudaFuncSetAttribute(flash_attn_tc_kernel,
                         cudaFuncAttributeMaxDynamicSharedMemorySize, AT_SMEM);

    __half *xh, *xl, *wq, *wo, *ah, *al;
    cudaGetSymbolAddress((void**)&xh, g_x_hi);
    cudaGetSymbolAddress((void**)&xl, g_x_lo);
    cudaGetSymbolAddress((void**)&wq, g_wq);
    cudaGetSymbolAddress((void**)&wo, g_wo);
    cudaGetSymbolAddress((void**)&ah, g_a_hi);
    cudaGetSymbolAddress((void**)&al, g_a_lo);

    // 1. Split x (fp16 hi/lo)
    split_kernel<<<(MROWS * DD / 4 + 255) / 256, 256>>>(x, xh, xl, MROWS * DD / 4);
    // 2. Transpose weights -> single fp16 [N,K]
    transpose_h_kernel<<<dim3(QKV_N / 32, DD / 32), 256>>>(w_qkv, wq, DD, QKV_N);
    transpose_h_kernel<<<dim3(DD / 32, DD / 32), 256>>>(w_out, wo, DD, DD);
    // 3. QKV projection -> q split / k single / v split
    gemm_mma_kernel<<<dim3(QKV_N / 128, MROWS / 128), 256, GEMM_SMEM>>>(
        xh, xl, wq, b_qkv, nullptr, QKV_N, 1);
    // 4. Flash attention -> attn output split
    flash_attn_tc_kernel<<<dim3(TT / 128, BB * HH), 256, AT_SMEM>>>();
    // 5. Output projection
    gemm_mma_kernel<<<dim3(DD / 128, MROWS / 128), 256, GEMM_SMEM>>>(
        ah, al, wo, b_out, out, DD, 0);
}

// round 8
// speedup vs baseline: 5.9443x; 1.6637x over previous
#include <cuda_runtime.h>
#include <cuda_fp16.h>
#include <math.h>
#include <stdint.h>

// Problem constants
constexpr int BB = 2;
constexpr int TT = 2048;
constexpr int DD = 1024;
constexpr int HH = 16;
constexpr int DH = 64;
constexpr int MROWS = BB * TT;          // 4096
constexpr int QKV_N = 3 * DD;           // 3072

// ---------------------------------------------------------------------------
// Scratch (static device allocations)
// ---------------------------------------------------------------------------
__device__ __half g_x[MROWS * DD];             // x fp16
__device__ __half g_wq[QKV_N * DD];            // w_qkv^T [N,K] fp16
__device__ __half g_wo[DD * DD];               // w_out^T [N,K] fp16
// layout [(b*16+h)][T][64]
__device__ __half g_q[BB*HH*TT*DH];
__device__ __half g_k[BB*HH*TT*DH];
__device__ __half g_v[BB*HH*TT*DH];
// attention output, layout [b*T+t][h*64+dh]
__device__ __half g_attn[MROWS * DD];

// ---------------------------------------------------------------------------
// PTX helpers
// ---------------------------------------------------------------------------
__device__ __forceinline__ uint32_t smem_u32(const void* p) {
    return (uint32_t)__cvta_generic_to_shared((void*)p);
}
__device__ __forceinline__ void cp16(uint32_t dst, const void* src) {
    asm volatile("cp.async.cg.shared.global [%0], [%1], 16;" :: "r"(dst), "l"(src));
}
__device__ __forceinline__ void ldsm4(uint32_t* r, uint32_t addr) {
    asm volatile("ldmatrix.sync.aligned.m8n8.x4.shared.b16 {%0,%1,%2,%3}, [%4];"
                 : "=r"(r[0]), "=r"(r[1]), "=r"(r[2]), "=r"(r[3]) : "r"(addr));
}
__device__ __forceinline__ void ldsm4t(uint32_t* r, uint32_t addr) {
    asm volatile("ldmatrix.sync.aligned.m8n8.x4.trans.shared.b16 {%0,%1,%2,%3}, [%4];"
                 : "=r"(r[0]), "=r"(r[1]), "=r"(r[2]), "=r"(r[3]) : "r"(addr));
}
__device__ __forceinline__ void mma_f16(float* d, const uint32_t* a,
                                        uint32_t b0, uint32_t b1) {
    asm volatile(
        "mma.sync.aligned.m16n8k16.row.col.f32.f16.f16.f32 "
        "{%0,%1,%2,%3}, {%4,%5,%6,%7}, {%8,%9}, {%0,%1,%2,%3};"
        : "+f"(d[0]), "+f"(d[1]), "+f"(d[2]), "+f"(d[3])
        : "r"(a[0]), "r"(a[1]), "r"(a[2]), "r"(a[3]), "r"(b0), "r"(b1));
}

// FFMA-only exp (no MUFU)
__device__ __forceinline__ float fast_exp(float x) {
    x = fmaxf(x, -80.f);
    float t = x * 1.44269504f;
    float r = t + 12582912.f;
    int   n = __float_as_int(r) - 0x4B400000;
    float f = t - (r - 12582912.f);
    float u = f * 0.69314718f;
    float p = 1.f + u * (1.f + u * (0.5f + u * (0.16666667f +
              u * (0.041666667f + u * 0.0083333333f))));
    return __int_as_float(__float_as_int(p) + (n << 23));
}

__device__ __forceinline__ uint32_t h2pack(float x, float y) {
    __half2 h = __floats2half2_rn(x, y);
    return *(uint32_t*)&h;
}

// ---------------------------------------------------------------------------
// Conversions
// ---------------------------------------------------------------------------
__global__ __launch_bounds__(256) void cast_kernel(
    const float* __restrict__ in, __half* __restrict__ out, int n4)
{
    int i = blockIdx.x * blockDim.x + threadIdx.x;
    if (i >= n4) return;
    float4 v = ((const float4*)in)[i];
    uint2 o;
    o.x = h2pack(v.x, v.y);
    o.y = h2pack(v.z, v.w);
    ((uint2*)out)[i] = o;
}

// [K,N] fp32 -> [N,K] fp16
__global__ __launch_bounds__(256) void transpose_h_kernel(
    const float* __restrict__ in, __half* __restrict__ out, int K, int N)
{
    __shared__ float tile[32][33];
    int n0 = blockIdx.x * 32, k0 = blockIdx.y * 32;
    int tx = threadIdx.x & 31, ty = threadIdx.x >> 5;
#pragma unroll
    for (int j = 0; j < 32; j += 8)
        tile[ty + j][tx] = in[(size_t)(k0 + ty + j) * N + n0 + tx];
    __syncthreads();
#pragma unroll
    for (int j = 0; j < 32; j += 8)
        out[(size_t)(n0 + ty + j) * K + k0 + tx] = __float2half_rn(tile[tx][ty + j]);
}

// ---------------------------------------------------------------------------
// fp16 single-pass GEMM: C = A @ B^T + bias.
// 128x128 tile, BK=64, 256 threads (8 warps 4x2), 2-stage cp.async.
// smem: 2 stages x {A, B}, each 128 rows x 144B.
// mode 0: fp32 out + bias. mode 1: QKV epilogue (q scaled, k, v fp16).
// ---------------------------------------------------------------------------
constexpr int ROW_B = 144;
constexpr int TILE_SM = 128 * ROW_B;      // 18432
constexpr int STAGE_SM = 2 * TILE_SM;     // 36864
constexpr int GEMM_SMEM = 2 * STAGE_SM;   // 73728
constexpr int NCHUNK_G = DD / 64;         // 16

__global__ __launch_bounds__(256, 2) void gemm_mma_kernel(
    const __half* __restrict__ A, const __half* __restrict__ Bw,
    const float* __restrict__ bias, float* __restrict__ C, int N, int mode)
{
    extern __shared__ char sm[];
    const uint32_t smb = smem_u32(sm);
    const int tid = threadIdx.x;
    const int wid = tid >> 5, lane = tid & 31;
    const int wm = wid >> 1, wn = wid & 1;
    const int m0 = blockIdx.y * 128;
    const int n0 = blockIdx.x * 128;

    const char* Ap = (const char*)A  + (size_t)m0 * DD * 2;
    const char* Bp = (const char*)Bw + (size_t)n0 * DD * 2;

    auto load_stage = [&](int c, int s) {
        const int k0b = c * 128;              // 64 fp16 = 128B
        const uint32_t sb = smb + s * STAGE_SM;
#pragma unroll
        for (int i = 0; i < 4; ++i) {
            const int cid = i * 256 + tid;    // 0..1023
            const int r = cid >> 3, c8 = (cid & 7) * 16;
            const size_t g = (size_t)r * 2048 + k0b + c8;
            const uint32_t so = r * ROW_B + c8;
            cp16(sb + so,           Ap + g);
            cp16(sb + TILE_SM + so, Bp + g);
        }
        asm volatile("cp.async.commit_group;" ::: "memory");
    };

    float acc[2][8][4];
#pragma unroll
    for (int mt = 0; mt < 2; ++mt)
#pragma unroll
        for (int nt = 0; nt < 8; ++nt)
#pragma unroll
            for (int j = 0; j < 4; ++j) acc[mt][nt][j] = 0.f;

    const int a_row = wm * 32 + (lane & 15);
    const int a_kb  = (lane >> 4) * 16;
    const int b_row = wn * 64 + (lane & 7) + ((lane >> 4) << 3);
    const int b_kb  = ((lane >> 3) & 1) * 16;

    load_stage(0, 0);

    for (int c = 0; c < NCHUNK_G; ++c) {
        if (c + 1 < NCHUNK_G) {
            load_stage(c + 1, (c + 1) & 1);
            asm volatile("cp.async.wait_group 1;" ::: "memory");
        } else {
            asm volatile("cp.async.wait_group 0;" ::: "memory");
        }
        __syncthreads();

        const uint32_t sb = smb + (c & 1) * STAGE_SM;
#pragma unroll
        for (int k16 = 0; k16 < 4; ++k16) {
            const int kb = k16 * 32;
            uint32_t ah[2][4], bw[4][4];
#pragma unroll
            for (int mt = 0; mt < 2; ++mt)
                ldsm4(ah[mt], sb + (a_row + mt * 16) * ROW_B + kb + a_kb);
#pragma unroll
            for (int p = 0; p < 4; ++p)
                ldsm4(bw[p], sb + TILE_SM + (b_row + p * 16) * ROW_B + kb + b_kb);
#pragma unroll
            for (int mt = 0; mt < 2; ++mt)
#pragma unroll
                for (int nt = 0; nt < 8; ++nt) {
                    const int p = nt >> 1, h = (nt & 1) * 2;
                    mma_f16(acc[mt][nt], ah[mt], bw[p][h], bw[p][h + 1]);
                }
        }
        __syncthreads();
    }

    if (mode == 0) {
#pragma unroll
        for (int mt = 0; mt < 2; ++mt) {
            const int r0 = m0 + wm * 32 + mt * 16 + (lane >> 2);
#pragma unroll
            for (int nt = 0; nt < 8; ++nt) {
                const int cc = n0 + wn * 64 + nt * 8 + (lane & 3) * 2;
                const float2 b2 = *(const float2*)(bias + cc);
                *(float2*)(C + (size_t)r0 * N + cc) =
                    make_float2(acc[mt][nt][0] + b2.x, acc[mt][nt][1] + b2.y);
                *(float2*)(C + (size_t)(r0 + 8) * N + cc) =
                    make_float2(acc[mt][nt][2] + b2.x, acc[mt][nt][3] + b2.y);
            }
        }
    } else {
        // QKV epilogue: q (x0.125) / k / v, all fp16, layout [(b*16+h)][t][dh]
        const int which = n0 >> 10;
        __half* dst = (which == 0) ? g_q : (which == 1) ? g_k : g_v;
        const float sc = (which == 0) ? 0.125f : 1.f;
#pragma unroll
        for (int mt = 0; mt < 2; ++mt) {
            const int r0 = m0 + wm * 32 + mt * 16 + (lane >> 2);
#pragma unroll
            for (int nt = 0; nt < 8; ++nt) {
                const int cc = n0 + wn * 64 + nt * 8 + (lane & 3) * 2;
                const int h = (cc & 1023) >> 6, dh = cc & 63;
                const float2 b2 = *(const float2*)(bias + cc);
#pragma unroll
                for (int half_i = 0; half_i < 2; ++half_i) {
                    const int r = r0 + half_i * 8;
                    const int bq = r >> 11, tq = r & 2047;
                    const size_t off = ((size_t)(bq * 16 + h) * 2048 + tq) * 64 + dh;
                    *(uint32_t*)(dst + off) =
                        h2pack((acc[mt][nt][2 * half_i] + b2.x) * sc,
                               (acc[mt][nt][2 * half_i + 1] + b2.y) * sc);
                }
            }
        }
    }
}

// ---------------------------------------------------------------------------
// Tensor-core flash attention, causal, fp16 single-pass.
// CTA: 128 q rows, 8 warps (16 rows each), KV tiles of 64, 2-stage cp.async.
// smem: Q [128][144B] + 2 stages x {K, V}[64][144B]  = 55296 B.
// ---------------------------------------------------------------------------
constexpr int AT_STG_OFF = 18432;
constexpr int AT_ARR     = 64 * ROW_B;        // 9216
constexpr int AT_STG     = 2 * AT_ARR;        // 18432
constexpr int AT_SMEM    = AT_STG_OFF + 2 * AT_STG;   // 55296

__global__ __launch_bounds__(256, 2) void flash_attn_tc_kernel()
{
    extern __shared__ char sm[];
    const uint32_t smb = smem_u32(sm);
    const int tid = threadIdx.x, wid = tid >> 5, lane = tid & 31;
    const int bx = (int)gridDim.x - 1 - (int)blockIdx.x;   // heavy blocks first
    const int i0 = bx * 128;
    const int ntile = 2 * bx + 2;
    const int bh = blockIdx.y;
    const size_t head2 = (size_t)bh * TT * DH * 2;

    const char* q_g = (const char*)g_q + head2 + (size_t)i0 * DH * 2;
    const char* k_g = (const char*)g_k + head2;
    const char* v_g = (const char*)g_v + head2;

#pragma unroll
    for (int it = 0; it < 4; ++it) {
        int cid = it * 256 + tid;
        int row = cid >> 3, c8 = (cid & 7) * 16;
        cp16(smb + row * ROW_B + c8, q_g + row * 128 + c8);
    }
    asm volatile("cp.async.commit_group;" ::: "memory");

    auto load_kv = [&](int t, int s) {
        const uint32_t sb = smb + AT_STG_OFF + s * AT_STG;
        const int j0b = t * 64 * 128;
#pragma unroll
        for (int it = 0; it < 2; ++it) {
            int cid = it * 256 + tid;
            int row = cid >> 3, c8 = (cid & 7) * 16;
            uint32_t so = row * ROW_B + c8;
            int go = j0b + row * 128 + c8;
            cp16(sb + so,          k_g + go);
            cp16(sb + AT_ARR + so, v_g + go);
        }
        asm volatile("cp.async.commit_group;" ::: "memory");
    };
    load_kv(0, 0);

    asm volatile("cp.async.wait_group 1;" ::: "memory");
    __syncthreads();
    uint32_t qf[4][4];
    {
        const uint32_t a_off = (wid * 16 + (lane & 15)) * ROW_B + (lane >> 4) * 16;
#pragma unroll
        for (int kc = 0; kc < 4; ++kc)
            ldsm4(qf[kc], smb + a_off + kc * 32);
    }

    float oacc[8][4];
#pragma unroll
    for (int nt = 0; nt < 8; ++nt)
#pragma unroll
        for (int j = 0; j < 4; ++j) oacc[nt][j] = 0.f;
    float mrow[2] = {-1e30f, -1e30f}, lrow[2] = {0.f, 0.f};

    const uint32_t kb_off = ((lane & 7) + ((lane >> 4) << 3)) * ROW_B +
                            ((lane >> 3) & 1) * 16;
    const uint32_t vrow = (lane & 7) + (((lane >> 3) & 1) << 3);
    const uint32_t vcol = (lane >> 4) * 16;

    for (int t = 0; t < ntile; ++t) {
        if (t + 1 < ntile) {
            load_kv(t + 1, (t + 1) & 1);
            asm volatile("cp.async.wait_group 1;" ::: "memory");
        } else {
            asm volatile("cp.async.wait_group 0;" ::: "memory");
        }
        __syncthreads();
        const uint32_t sb = smb + AT_STG_OFF + (t & 1) * AT_STG;
        const int j0 = t * 64;

        // S = Q @ K^T
        float sacc[8][4];
#pragma unroll
        for (int nt = 0; nt < 8; ++nt)
#pragma unroll
            for (int j = 0; j < 4; ++j) sacc[nt][j] = 0.f;

#pragma unroll
        for (int kc = 0; kc < 4; ++kc) {
#pragma unroll
            for (int p = 0; p < 4; ++p) {
                uint32_t kh4[4];
                ldsm4(kh4, sb + kb_off + p * (16 * ROW_B) + kc * 32);
                mma_f16(sacc[2 * p],     qf[kc], kh4[0], kh4[1]);
                mma_f16(sacc[2 * p + 1], qf[kc], kh4[2], kh4[3]);
            }
        }

        // causal mask
        if (j0 + 63 > i0 + wid * 16) {
#pragma unroll
            for (int i = 0; i < 2; ++i) {
                const int qi = i0 + wid * 16 + (lane >> 2) + 8 * i;
#pragma unroll
                for (int nt = 0; nt < 8; ++nt) {
                    const int kt0 = j0 + nt * 8 + (lane & 3) * 2;
                    if (kt0 > qi)     sacc[nt][2 * i]     = -1e30f;
                    if (kt0 + 1 > qi) sacc[nt][2 * i + 1] = -1e30f;
                }
            }
        }

        // online softmax
#pragma unroll
        for (int i = 0; i < 2; ++i) {
            float mx = -1e30f;
#pragma unroll
            for (int nt = 0; nt < 8; ++nt)
                mx = fmaxf(mx, fmaxf(sacc[nt][2 * i], sacc[nt][2 * i + 1]));
            mx = fmaxf(mx, __shfl_xor_sync(0xffffffffu, mx, 1));
            mx = fmaxf(mx, __shfl_xor_sync(0xffffffffu, mx, 2));
            const float mn = fmaxf(mrow[i], mx);
            const float al = fast_exp(mrow[i] - mn);
            mrow[i] = mn;
            float sum = 0.f;
#pragma unroll
            for (int nt = 0; nt < 8; ++nt) {
                float p0 = fast_exp(sacc[nt][2 * i] - mn);
                float p1 = fast_exp(sacc[nt][2 * i + 1] - mn);
                sacc[nt][2 * i] = p0;
                sacc[nt][2 * i + 1] = p1;
                sum += p0 + p1;
            }
            sum += __shfl_xor_sync(0xffffffffu, sum, 1);
            sum += __shfl_xor_sync(0xffffffffu, sum, 2);
            lrow[i] = lrow[i] * al + sum;
#pragma unroll
            for (int nt = 0; nt < 8; ++nt) {
                oacc[nt][2 * i] *= al;
                oacc[nt][2 * i + 1] *= al;
            }
        }

        // O += P @ V
#pragma unroll
        for (int kt = 0; kt < 4; ++kt) {
            uint32_t pa[4];
            pa[0] = h2pack(sacc[2 * kt][0],     sacc[2 * kt][1]);
            pa[1] = h2pack(sacc[2 * kt][2],     sacc[2 * kt][3]);
            pa[2] = h2pack(sacc[2 * kt + 1][0], sacc[2 * kt + 1][1]);
            pa[3] = h2pack(sacc[2 * kt + 1][2], sacc[2 * kt + 1][3]);
#pragma unroll
            for (int vd = 0; vd < 4; ++vd) {
                uint32_t vh4[4];
                ldsm4t(vh4, sb + AT_ARR + (kt * 16 + vrow) * ROW_B + vcol + vd * 32);
                mma_f16(oacc[2 * vd],     pa, vh4[0], vh4[1]);
                mma_f16(oacc[2 * vd + 1], pa, vh4[2], vh4[3]);
            }
        }
        __syncthreads();
    }

    // epilogue: normalize, write fp16 [b*T+t][h*64+dh]
    const int b = bh >> 4, h = bh & 15;
#pragma unroll
    for (int i = 0; i < 2; ++i) {
        const float inv = 1.0f / lrow[i];
        const int trow = i0 + wid * 16 + (lane >> 2) + 8 * i;
        const size_t rbase = (size_t)(b * TT + trow) * DD + h * 64;
#pragma unroll
        for (int nt = 0; nt < 8; ++nt) {
            const int col = nt * 8 + (lane & 3) * 2;
            *(uint32_t*)(g_attn + rbase + col) =
                h2pack(oacc[nt][2 * i] * inv, oacc[nt][2 * i + 1] * inv);
        }
    }
}

// ---------------------------------------------------------------------------
extern "C" void kernel_launch(void* const* d_in, const int* in_sizes, int n_in,
                              void* d_out, int out_size)
{
    const float* x     = (const float*)d_in[0];
    const float* w_qkv = (const float*)d_in[1];
    const float* b_qkv = (const float*)d_in[2];
    const float* w_out = (const float*)d_in[3];
    const float* b_out = (const float*)d_in[4];
    float* out = (float*)d_out;

    cudaFuncSetAttribute(gemm_mma_kernel,
                         cudaFuncAttributeMaxDynamicSharedMemorySize, GEMM_SMEM);
    cudaFuncSetAttribute(flash_attn_tc_kernel,
                         cudaFuncAttributeMaxDynamicSharedMemorySize, AT_SMEM);

    __half *xh, *wq, *wo, *ah;
    cudaGetSymbolAddress((void**)&xh, g_x);
    cudaGetSymbolAddress((void**)&wq, g_wq);
    cudaGetSymbolAddress((void**)&wo, g_wo);
    cudaGetSymbolAddress((void**)&ah, g_attn);

    // 1. Cast x -> fp16
    cast_kernel<<<(MROWS * DD / 4 + 255) / 256, 256>>>(x, xh, MROWS * DD / 4);
    // 2. Transpose weights -> fp16 [N,K]
    transpose_h_kernel<<<dim3(QKV_N / 32, DD / 32), 256>>>(w_qkv, wq, DD, QKV_N);
    transpose_h_kernel<<<dim3(DD / 32, DD / 32), 256>>>(w_out, wo, DD, DD);
    // 3. QKV projection -> q/k/v fp16 (q pre-scaled)
    gemm_mma_kernel<<<dim3(QKV_N / 128, MROWS / 128), 256, GEMM_SMEM>>>(
        xh, wq, b_qkv, nullptr, QKV_N, 1);
    // 4. Flash attention -> attn fp16
    flash_attn_tc_kernel<<<dim3(TT / 128, BB * HH), 256, AT_SMEM>>>();
    // 5. Output projection (fp32 out)
    gemm_mma_kernel<<<dim3(DD / 128, MROWS / 128), 256, GEMM_SMEM>>>(
        ah, wo, b_out, out, DD, 0);
}

// round 9
// speedup vs baseline: 6.0681x; 1.0208x over previous
#include <cuda_runtime.h>
#include <cuda_fp16.h>
#include <math.h>
#include <stdint.h>

// Problem constants
constexpr int BB = 2;
constexpr int TT = 2048;
constexpr int DD = 1024;
constexpr int HH = 16;
constexpr int DH = 64;
constexpr int MROWS = BB * TT;          // 4096
constexpr int QKV_N = 3 * DD;           // 3072

// ---------------------------------------------------------------------------
// Scratch (static device allocations)
// ---------------------------------------------------------------------------
__device__ __half g_x[MROWS * DD];             // x fp16
__device__ __half g_wq[QKV_N * DD];            // w_qkv^T [N,K] fp16
__device__ __half g_wo[DD * DD];               // w_out^T [N,K] fp16
// layout [(b*16+h)][T][64]
__device__ __half g_q[BB*HH*TT*DH];
__device__ __half g_k[BB*HH*TT*DH];
__device__ __half g_v[BB*HH*TT*DH];
// attention output, layout [b*T+t][h*64+dh]
__device__ __half g_attn[MROWS * DD];

// ---------------------------------------------------------------------------
// PTX helpers
// ---------------------------------------------------------------------------
__device__ __forceinline__ uint32_t smem_u32(const void* p) {
    return (uint32_t)__cvta_generic_to_shared((void*)p);
}
__device__ __forceinline__ void cp16(uint32_t dst, const void* src) {
    asm volatile("cp.async.cg.shared.global [%0], [%1], 16;" :: "r"(dst), "l"(src));
}
__device__ __forceinline__ void ldsm4(uint32_t* r, uint32_t addr) {
    asm volatile("ldmatrix.sync.aligned.m8n8.x4.shared.b16 {%0,%1,%2,%3}, [%4];"
                 : "=r"(r[0]), "=r"(r[1]), "=r"(r[2]), "=r"(r[3]) : "r"(addr));
}
__device__ __forceinline__ void ldsm4t(uint32_t* r, uint32_t addr) {
    asm volatile("ldmatrix.sync.aligned.m8n8.x4.trans.shared.b16 {%0,%1,%2,%3}, [%4];"
                 : "=r"(r[0]), "=r"(r[1]), "=r"(r[2]), "=r"(r[3]) : "r"(addr));
}
__device__ __forceinline__ void mma_f16(float* d, const uint32_t* a,
                                        uint32_t b0, uint32_t b1) {
    asm volatile(
        "mma.sync.aligned.m16n8k16.row.col.f32.f16.f16.f32 "
        "{%0,%1,%2,%3}, {%4,%5,%6,%7}, {%8,%9}, {%0,%1,%2,%3};"
        : "+f"(d[0]), "+f"(d[1]), "+f"(d[2]), "+f"(d[3])
        : "r"(a[0]), "r"(a[1]), "r"(a[2]), "r"(a[3]), "r"(b0), "r"(b1));
}

// FFMA-only exp2 (no MUFU). Input already in log2 domain.
__device__ __forceinline__ float fast_exp2(float x) {
    x = fmaxf(x, -120.f);
    float r = x + 12582912.f;                    // round to nearest int
    int   n = __float_as_int(r) - 0x4B400000;
    float f = x - (r - 12582912.f);              // f in [-0.5, 0.5]
    float p = 1.f + f * (0.693147180f + f * (0.240226507f + f * (0.0555041087f +
              f * (0.00961812911f + f * 0.00133335581f))));
    return __int_as_float(__float_as_int(p) + (n << 23));
}

__device__ __forceinline__ uint32_t h2pack(float x, float y) {
    __half2 h = __floats2half2_rn(x, y);
    return *(uint32_t*)&h;
}

// ---------------------------------------------------------------------------
// Conversions
// ---------------------------------------------------------------------------
__global__ __launch_bounds__(256) void cast_kernel(
    const float* __restrict__ in, __half* __restrict__ out, int n4)
{
    int i = blockIdx.x * blockDim.x + threadIdx.x;
    if (i >= n4) return;
    float4 v = ((const float4*)in)[i];
    uint2 o;
    o.x = h2pack(v.x, v.y);
    o.y = h2pack(v.z, v.w);
    ((uint2*)out)[i] = o;
}

// [K,N] fp32 -> [N,K] fp16
__global__ __launch_bounds__(256) void transpose_h_kernel(
    const float* __restrict__ in, __half* __restrict__ out, int K, int N)
{
    __shared__ float tile[32][33];
    int n0 = blockIdx.x * 32, k0 = blockIdx.y * 32;
    int tx = threadIdx.x & 31, ty = threadIdx.x >> 5;
#pragma unroll
    for (int j = 0; j < 32; j += 8)
        tile[ty + j][tx] = in[(size_t)(k0 + ty + j) * N + n0 + tx];
    __syncthreads();
#pragma unroll
    for (int j = 0; j < 32; j += 8)
        out[(size_t)(n0 + ty + j) * K + k0 + tx] = __float2half_rn(tile[tx][ty + j]);
}

// ---------------------------------------------------------------------------
// fp16 single-pass GEMM: C = A @ B^T + bias.
// 128x128 tile, BK=64, 256 threads (8 warps 4x2), 2-stage cp.async,
// ONE __syncthreads per K-chunk (wait -> sync -> issue next -> compute).
// ---------------------------------------------------------------------------
constexpr int ROW_B = 144;
constexpr int TILE_SM = 128 * ROW_B;      // 18432
constexpr int STAGE_SM = 2 * TILE_SM;     // 36864
constexpr int GEMM_SMEM = 2 * STAGE_SM;   // 73728
constexpr int NCHUNK_G = DD / 64;         // 16

// Q scale folded with log2(e) so attention can use exp2 directly.
constexpr float QSCALE = 0.125f * 1.44269504088896f;

__global__ __launch_bounds__(256, 2) void gemm_mma_kernel(
    const __half* __restrict__ A, const __half* __restrict__ Bw,
    const float* __restrict__ bias, float* __restrict__ C, int N, int mode)
{
    extern __shared__ char sm[];
    const uint32_t smb = smem_u32(sm);
    const int tid = threadIdx.x;
    const int wid = tid >> 5, lane = tid & 31;
    const int wm = wid >> 1, wn = wid & 1;
    const int m0 = blockIdx.y * 128;
    const int n0 = blockIdx.x * 128;

    const char* Ap = (const char*)A  + (size_t)m0 * DD * 2;
    const char* Bp = (const char*)Bw + (size_t)n0 * DD * 2;

    auto load_stage = [&](int c, int s) {
        const int k0b = c * 128;              // 64 fp16 = 128B
        const uint32_t sb = smb + s * STAGE_SM;
#pragma unroll
        for (int i = 0; i < 4; ++i) {
            const int cid = i * 256 + tid;    // 0..1023
            const int r = cid >> 3, c8 = (cid & 7) * 16;
            const size_t g = (size_t)r * 2048 + k0b + c8;
            const uint32_t so = r * ROW_B + c8;
            cp16(sb + so,           Ap + g);
            cp16(sb + TILE_SM + so, Bp + g);
        }
        asm volatile("cp.async.commit_group;" ::: "memory");
    };

    float acc[2][8][4];
#pragma unroll
    for (int mt = 0; mt < 2; ++mt)
#pragma unroll
        for (int nt = 0; nt < 8; ++nt)
#pragma unroll
            for (int j = 0; j < 4; ++j) acc[mt][nt][j] = 0.f;

    const int a_row = wm * 32 + (lane & 15);
    const int a_kb  = (lane >> 4) * 16;
    const int b_row = wn * 64 + (lane & 7) + ((lane >> 4) << 3);
    const int b_kb  = ((lane >> 3) & 1) * 16;

    load_stage(0, 0);

    for (int c = 0; c < NCHUNK_G; ++c) {
        asm volatile("cp.async.wait_group 0;" ::: "memory");
        __syncthreads();
        if (c + 1 < NCHUNK_G) load_stage(c + 1, (c + 1) & 1);

        const uint32_t sb = smb + (c & 1) * STAGE_SM;
#pragma unroll
        for (int k16 = 0; k16 < 4; ++k16) {
            const int kb = k16 * 32;
            uint32_t ah[2][4], bw[4][4];
#pragma unroll
            for (int mt = 0; mt < 2; ++mt)
                ldsm4(ah[mt], sb + (a_row + mt * 16) * ROW_B + kb + a_kb);
#pragma unroll
            for (int p = 0; p < 4; ++p)
                ldsm4(bw[p], sb + TILE_SM + (b_row + p * 16) * ROW_B + kb + b_kb);
#pragma unroll
            for (int mt = 0; mt < 2; ++mt)
#pragma unroll
                for (int nt = 0; nt < 8; ++nt) {
                    const int p = nt >> 1, h = (nt & 1) * 2;
                    mma_f16(acc[mt][nt], ah[mt], bw[p][h], bw[p][h + 1]);
                }
        }
    }

    if (mode == 0) {
#pragma unroll
        for (int mt = 0; mt < 2; ++mt) {
            const int r0 = m0 + wm * 32 + mt * 16 + (lane >> 2);
#pragma unroll
            for (int nt = 0; nt < 8; ++nt) {
                const int cc = n0 + wn * 64 + nt * 8 + (lane & 3) * 2;
                const float2 b2 = *(const float2*)(bias + cc);
                *(float2*)(C + (size_t)r0 * N + cc) =
                    make_float2(acc[mt][nt][0] + b2.x, acc[mt][nt][1] + b2.y);
                *(float2*)(C + (size_t)(r0 + 8) * N + cc) =
                    make_float2(acc[mt][nt][2] + b2.x, acc[mt][nt][3] + b2.y);
            }
        }
    } else {
        // QKV epilogue: q (xQSCALE, log2 domain) / k / v, fp16
        const int which = n0 >> 10;
        __half* dst = (which == 0) ? g_q : (which == 1) ? g_k : g_v;
        const float sc = (which == 0) ? QSCALE : 1.f;
#pragma unroll
        for (int mt = 0; mt < 2; ++mt) {
            const int r0 = m0 + wm * 32 + mt * 16 + (lane >> 2);
#pragma unroll
            for (int nt = 0; nt < 8; ++nt) {
                const int cc = n0 + wn * 64 + nt * 8 + (lane & 3) * 2;
                const int h = (cc & 1023) >> 6, dh = cc & 63;
                const float2 b2 = *(const float2*)(bias + cc);
#pragma unroll
                for (int half_i = 0; half_i < 2; ++half_i) {
                    const int r = r0 + half_i * 8;
                    const int bq = r >> 11, tq = r & 2047;
                    const size_t off = ((size_t)(bq * 16 + h) * 2048 + tq) * 64 + dh;
                    *(uint32_t*)(dst + off) =
                        h2pack((acc[mt][nt][2 * half_i] + b2.x) * sc,
                               (acc[mt][nt][2 * half_i + 1] + b2.y) * sc);
                }
            }
        }
    }
}

// ---------------------------------------------------------------------------
// Tensor-core flash attention, causal, fp16, exp2-domain softmax.
// CTA: 128 q rows, 8 warps (16 rows each), KV tiles of 64, 2-stage cp.async,
// ONE __syncthreads per KV tile.
// smem: Q [128][144B] + 2 stages x {K, V}[64][144B]  = 55296 B.
// ---------------------------------------------------------------------------
constexpr int AT_STG_OFF = 18432;
constexpr int AT_ARR     = 64 * ROW_B;        // 9216
constexpr int AT_STG     = 2 * AT_ARR;        // 18432
constexpr int AT_SMEM    = AT_STG_OFF + 2 * AT_STG;   // 55296

__global__ __launch_bounds__(256, 2) void flash_attn_tc_kernel()
{
    extern __shared__ char sm[];
    const uint32_t smb = smem_u32(sm);
    const int tid = threadIdx.x, wid = tid >> 5, lane = tid & 31;
    const int bx = (int)gridDim.x - 1 - (int)blockIdx.x;   // heavy blocks first
    const int i0 = bx * 128;
    const int ntile = 2 * bx + 2;
    const int bh = blockIdx.y;
    const size_t head2 = (size_t)bh * TT * DH * 2;

    const char* q_g = (const char*)g_q + head2 + (size_t)i0 * DH * 2;
    const char* k_g = (const char*)g_k + head2;
    const char* v_g = (const char*)g_v + head2;

#pragma unroll
    for (int it = 0; it < 4; ++it) {
        int cid = it * 256 + tid;
        int row = cid >> 3, c8 = (cid & 7) * 16;
        cp16(smb + row * ROW_B + c8, q_g + row * 128 + c8);
    }
    asm volatile("cp.async.commit_group;" ::: "memory");

    auto load_kv = [&](int t, int s) {
        const uint32_t sb = smb + AT_STG_OFF + s * AT_STG;
        const int j0b = t * 64 * 128;
#pragma unroll
        for (int it = 0; it < 2; ++it) {
            int cid = it * 256 + tid;
            int row = cid >> 3, c8 = (cid & 7) * 16;
            uint32_t so = row * ROW_B + c8;
            int go = j0b + row * 128 + c8;
            cp16(sb + so,          k_g + go);
            cp16(sb + AT_ARR + so, v_g + go);
        }
        asm volatile("cp.async.commit_group;" ::: "memory");
    };
    load_kv(0, 0);

    // Q fragments
    asm volatile("cp.async.wait_group 1;" ::: "memory");
    __syncthreads();
    uint32_t qf[4][4];
    {
        const uint32_t a_off = (wid * 16 + (lane & 15)) * ROW_B + (lane >> 4) * 16;
#pragma unroll
        for (int kc = 0; kc < 4; ++kc)
            ldsm4(qf[kc], smb + a_off + kc * 32);
    }

    float oacc[8][4];
#pragma unroll
    for (int nt = 0; nt < 8; ++nt)
#pragma unroll
        for (int j = 0; j < 4; ++j) oacc[nt][j] = 0.f;
    float mrow[2] = {-1e30f, -1e30f}, lrow[2] = {0.f, 0.f};

    const uint32_t kb_off = ((lane & 7) + ((lane >> 4) << 3)) * ROW_B +
                            ((lane >> 3) & 1) * 16;
    const uint32_t vrow = (lane & 7) + (((lane >> 3) & 1) << 3);
    const uint32_t vcol = (lane >> 4) * 16;

    for (int t = 0; t < ntile; ++t) {
        asm volatile("cp.async.wait_group 0;" ::: "memory");
        __syncthreads();
        if (t + 1 < ntile) load_kv(t + 1, (t + 1) & 1);

        const uint32_t sb = smb + AT_STG_OFF + (t & 1) * AT_STG;
        const int j0 = t * 64;

        // S = Q @ K^T (scores already in log2 domain via QSCALE)
        float sacc[8][4];
#pragma unroll
        for (int nt = 0; nt < 8; ++nt)
#pragma unroll
            for (int j = 0; j < 4; ++j) sacc[nt][j] = 0.f;

#pragma unroll
        for (int kc = 0; kc < 4; ++kc) {
#pragma unroll
            for (int p = 0; p < 4; ++p) {
                uint32_t kh4[4];
                ldsm4(kh4, sb + kb_off + p * (16 * ROW_B) + kc * 32);
                mma_f16(sacc[2 * p],     qf[kc], kh4[0], kh4[1]);
                mma_f16(sacc[2 * p + 1], qf[kc], kh4[2], kh4[3]);
            }
        }

        // causal mask
        if (j0 + 63 > i0 + wid * 16) {
#pragma unroll
            for (int i = 0; i < 2; ++i) {
                const int qi = i0 + wid * 16 + (lane >> 2) + 8 * i;
#pragma unroll
                for (int nt = 0; nt < 8; ++nt) {
                    const int kt0 = j0 + nt * 8 + (lane & 3) * 2;
                    if (kt0 > qi)     sacc[nt][2 * i]     = -1e30f;
                    if (kt0 + 1 > qi) sacc[nt][2 * i + 1] = -1e30f;
                }
            }
        }

        // online softmax (exp2 domain)
#pragma unroll
        for (int i = 0; i < 2; ++i) {
            float mx = -1e30f;
#pragma unroll
            for (int nt = 0; nt < 8; ++nt)
                mx = fmaxf(mx, fmaxf(sacc[nt][2 * i], sacc[nt][2 * i + 1]));
            mx = fmaxf(mx, __shfl_xor_sync(0xffffffffu, mx, 1));
            mx = fmaxf(mx, __shfl_xor_sync(0xffffffffu, mx, 2));
            const float mn = fmaxf(mrow[i], mx);
            const float al = fast_exp2(mrow[i] - mn);
            mrow[i] = mn;
            float sum = 0.f;
#pragma unroll
            for (int nt = 0; nt < 8; ++nt) {
                float p0 = fast_exp2(sacc[nt][2 * i] - mn);
                float p1 = fast_exp2(sacc[nt][2 * i + 1] - mn);
                sacc[nt][2 * i] = p0;
                sacc[nt][2 * i + 1] = p1;
                sum += p0 + p1;
            }
            sum += __shfl_xor_sync(0xffffffffu, sum, 1);
            sum += __shfl_xor_sync(0xffffffffu, sum, 2);
            lrow[i] = lrow[i] * al + sum;
#pragma unroll
            for (int nt = 0; nt < 8; ++nt) {
                oacc[nt][2 * i] *= al;
                oacc[nt][2 * i + 1] *= al;
            }
        }

        // O += P @ V
#pragma unroll
        for (int kt = 0; kt < 4; ++kt) {
            uint32_t pa[4];
            pa[0] = h2pack(sacc[2 * kt][0],     sacc[2 * kt][1]);
            pa[1] = h2pack(sacc[2 * kt][2],     sacc[2 * kt][3]);
            pa[2] = h2pack(sacc[2 * kt + 1][0], sacc[2 * kt + 1][1]);
            pa[3] = h2pack(sacc[2 * kt + 1][2], sacc[2 * kt + 1][3]);
#pragma unroll
            for (int vd = 0; vd < 4; ++vd) {
                uint32_t vh4[4];
                ldsm4t(vh4, sb + AT_ARR + (kt * 16 + vrow) * ROW_B + vcol + vd * 32);
                mma_f16(oacc[2 * vd],     pa, vh4[0], vh4[1]);
                mma_f16(oacc[2 * vd + 1], pa, vh4[2], vh4[3]);
            }
        }
    }

    // epilogue: normalize, write fp16 [b*T+t][h*64+dh]
    const int b = bh >> 4, h = bh & 15;
#pragma unroll
    for (int i = 0; i < 2; ++i) {
        const float inv = 1.0f / lrow[i];
        const int trow = i0 + wid * 16 + (lane >> 2) + 8 * i;
        const size_t rbase = (size_t)(b * TT + trow) * DD + h * 64;
#pragma unroll
        for (int nt = 0; nt < 8; ++nt) {
            const int col = nt * 8 + (lane & 3) * 2;
            *(uint32_t*)(g_attn + rbase + col) =
                h2pack(oacc[nt][2 * i] * inv, oacc[nt][2 * i + 1] * inv);
        }
    }
}

// ---------------------------------------------------------------------------
extern "C" void kernel_launch(void* const* d_in, const int* in_sizes, int n_in,
                              void* d_out, int out_size)
{
    const float* x     = (const float*)d_in[0];
    const float* w_qkv = (const float*)d_in[1];
    const float* b_qkv = (const float*)d_in[2];
    const float* w_out = (const float*)d_in[3];
    const float* b_out = (const float*)d_in[4];
    float* out = (float*)d_out;

    cudaFuncSetAttribute(gemm_mma_kernel,
                         cudaFuncAttributeMaxDynamicSharedMemorySize, GEMM_SMEM);
    cudaFuncSetAttribute(flash_attn_tc_kernel,
                         cudaFuncAttributeMaxDynamicSharedMemorySize, AT_SMEM);

    __half *xh, *wq, *wo, *ah;
    cudaGetSymbolAddress((void**)&xh, g_x);
    cudaGetSymbolAddress((void**)&wq, g_wq);
    cudaGetSymbolAddress((void**)&wo, g_wo);
    cudaGetSymbolAddress((void**)&ah, g_attn);

    // 1. Cast x -> fp16
    cast_kernel<<<(MROWS * DD / 4 + 255) / 256, 256>>>(x, xh, MROWS * DD / 4);
    // 2. Transpose weights -> fp16 [N,K]
    transpose_h_kernel<<<dim3(QKV_N / 32, DD / 32), 256>>>(w_qkv, wq, DD, QKV_N);
    transpose_h_kernel<<<dim3(DD / 32, DD / 32), 256>>>(w_out, wo, DD, DD);
    // 3. QKV projection -> q/k/v fp16 (q pre-scaled into log2 domain)
    gemm_mma_kernel<<<dim3(QKV_N / 128, MROWS / 128), 256, GEMM_SMEM>>>(
        xh, wq, b_qkv, nullptr, QKV_N, 1);
    // 4. Flash attention -> attn fp16
    flash_attn_tc_kernel<<<dim3(TT / 128, BB * HH), 256, AT_SMEM>>>();
    // 5. Output projection (fp32 out)
    gemm_mma_kernel<<<dim3(DD / 128, MROWS / 128), 256, GEMM_SMEM>>>(
        ah, wo, b_out, out, DD, 0);
}